// round 1
// baseline (speedup 1.0000x reference)
#include <cuda_runtime.h>
#include <math.h>

// Problem dimensions
#define BQ      4096        // query rows (B)
#define NEX     20000       // exemplar rows (N)
#define NPAD    20096       // padded exemplars: 157 * 128
#define FDIM    768         // feature dim (K of embed GEMM)
#define EDIM    512         // embed dim (N of embed GEMM, K of main GEMM)
#define TOTROWS (BQ + NPAD) // 24192 = 189 * 128
#define REALROWS (BQ + NEX) // 24096
#define NB_N    157         // n-blocks in main GEMM (20096/128)
#define NB_M    32          // m-blocks in main GEMM (4096/128)

// Scratch (zero-initialized at module load; pad rows never written -> stay 0)
__device__ float g_XDe[TOTROWS * EDIM];   // rows 0..4095 = Xe(normed), 4096.. = De(normed)
__device__ float g_rh[NPAD];              // rh[n], pad entries stay 0
__device__ float g_partial[NB_N * BQ];    // per-n-block partial logits

// ---------------------------------------------------------------------------
// Kernel 1: embed GEMM  C[row][e] = sum_f A[row][f] * g_w[e][f] + g_b[e]
// A = concat(X [4096x768], D [20000x768]); pad rows written as 0.
// Tile 128x128, BK=16, 256 threads, 8x8 per thread.
// ---------------------------------------------------------------------------
__global__ __launch_bounds__(256) void embed_gemm_kernel(
    const float* __restrict__ X, const float* __restrict__ D,
    const float* __restrict__ g_w, const float* __restrict__ g_b)
{
    __shared__ float As[16][128 + 4];
    __shared__ float Bs[16][128 + 4];

    const int m0 = blockIdx.x * 128;   // row tile (0..188)
    const int e0 = blockIdx.y * 128;   // embed tile (0..3)
    const int tid = threadIdx.x;
    const int tx = tid & 15;           // 0..15
    const int ty = tid >> 4;           // 0..15

    float acc[8][8];
#pragma unroll
    for (int i = 0; i < 8; i++)
#pragma unroll
        for (int j = 0; j < 8; j++) acc[i][j] = 0.f;

    for (int k0 = 0; k0 < FDIM; k0 += 16) {
        // Load A tile: [kk][m]
#pragma unroll
        for (int it = 0; it < 8; it++) {
            int idx = tid + it * 256;          // 0..2047
            int m = idx >> 4, kk = idx & 15;
            int row = m0 + m;
            float v = 0.f;
            if (row < REALROWS) {
                const float* src = (row < BQ) ? (X + (size_t)row * FDIM)
                                              : (D + (size_t)(row - BQ) * FDIM);
                v = src[k0 + kk];
            }
            As[kk][m] = v;
        }
        // Load B tile (g_w rows): [kk][e]
#pragma unroll
        for (int it = 0; it < 8; it++) {
            int idx = tid + it * 256;
            int e = idx >> 4, kk = idx & 15;
            Bs[kk][e] = g_w[(size_t)(e0 + e) * FDIM + k0 + kk];
        }
        __syncthreads();

#pragma unroll
        for (int kk = 0; kk < 16; kk++) {
            float a[8], b[8];
#pragma unroll
            for (int i = 0; i < 8; i++) a[i] = As[kk][ty + i * 16];
#pragma unroll
            for (int j = 0; j < 8; j++) b[j] = Bs[kk][tx + j * 16];
#pragma unroll
            for (int i = 0; i < 8; i++)
#pragma unroll
                for (int j = 0; j < 8; j++) acc[i][j] += a[i] * b[j];
        }
        __syncthreads();
    }

    // Write with bias; pad rows -> 0
#pragma unroll
    for (int i = 0; i < 8; i++) {
        int row = m0 + ty + i * 16;
#pragma unroll
        for (int j = 0; j < 8; j++) {
            int e = e0 + tx + j * 16;
            float v = (row < REALROWS) ? (acc[i][j] + g_b[e]) : 0.f;
            g_XDe[(size_t)row * EDIM + e] = v;
        }
    }
}

// ---------------------------------------------------------------------------
// Kernel 2: per-row L2 normalize (in place). One block of 128 threads per row.
// ---------------------------------------------------------------------------
__global__ __launch_bounds__(128) void normalize_kernel()
{
    const int row = blockIdx.x;           // 0..24095
    float* p = g_XDe + (size_t)row * EDIM;
    const int t = threadIdx.x;

    float v[4];
    float ss = 0.f;
#pragma unroll
    for (int i = 0; i < 4; i++) { v[i] = p[t + i * 128]; ss += v[i] * v[i]; }

    // reduce 128 threads
#pragma unroll
    for (int off = 16; off >= 1; off >>= 1)
        ss += __shfl_xor_sync(0xffffffffu, ss, off);
    __shared__ float red[4];
    if ((t & 31) == 0) red[t >> 5] = ss;
    __syncthreads();
    float tot = red[0] + red[1] + red[2] + red[3];
    float inv = 1.f / fmaxf(sqrtf(tot), 1e-12f);

#pragma unroll
    for (int i = 0; i < 4; i++) p[t + i * 128] = v[i] * inv;
}

// ---------------------------------------------------------------------------
// Kernel 3: rh[n] = (2*r[n]-1)*h_w + h_b  (n < 20000; pad stays 0)
// ---------------------------------------------------------------------------
__global__ void rh_kernel(const float* __restrict__ r,
                          const float* __restrict__ h_w,
                          const float* __restrict__ h_b)
{
    int n = blockIdx.x * blockDim.x + threadIdx.x;
    if (n < NEX)
        g_rh[n] = (2.f * r[n] - 1.f) * h_w[0] + h_b[0];
}

// ---------------------------------------------------------------------------
// Kernel 4: main fused GEMM + cube + rh-weighting + n-reduction.
// s[m][n] = Xen[m] . Den[n]  (K=512), contribution = s^3 * rh[n].
// Each CTA (128m x 128n) reduces to 128 row-partials -> g_partial[nb][m].
// ---------------------------------------------------------------------------
__global__ __launch_bounds__(256) void minerva_main_kernel()
{
    __shared__ float As[16][128 + 4];
    __shared__ float Bs[16][128 + 4];

    const int m0 = blockIdx.x * 128;   // query tile
    const int n0 = blockIdx.y * 128;   // exemplar tile
    const int tid = threadIdx.x;
    const int tx = tid & 15;
    const int ty = tid >> 4;

    const float* Abase = g_XDe;                       // query rows
    const float* Bbase = g_XDe + (size_t)BQ * EDIM;   // exemplar rows

    float acc[8][8];
#pragma unroll
    for (int i = 0; i < 8; i++)
#pragma unroll
        for (int j = 0; j < 8; j++) acc[i][j] = 0.f;

    for (int k0 = 0; k0 < EDIM; k0 += 16) {
#pragma unroll
        for (int it = 0; it < 8; it++) {
            int idx = tid + it * 256;
            int m = idx >> 4, kk = idx & 15;
            As[kk][m] = Abase[(size_t)(m0 + m) * EDIM + k0 + kk];
        }
#pragma unroll
        for (int it = 0; it < 8; it++) {
            int idx = tid + it * 256;
            int n = idx >> 4, kk = idx & 15;
            Bs[kk][n] = Bbase[(size_t)(n0 + n) * EDIM + k0 + kk];
        }
        __syncthreads();

#pragma unroll
        for (int kk = 0; kk < 16; kk++) {
            float a[8], b[8];
#pragma unroll
            for (int i = 0; i < 8; i++) a[i] = As[kk][ty + i * 16];
#pragma unroll
            for (int j = 0; j < 8; j++) b[j] = Bs[kk][tx + j * 16];
#pragma unroll
            for (int i = 0; i < 8; i++)
#pragma unroll
                for (int j = 0; j < 8; j++) acc[i][j] += a[i] * b[j];
        }
        __syncthreads();
    }

    // Epilogue: cube, weight by rh, reduce over n within the tile.
    float rhv[8];
#pragma unroll
    for (int j = 0; j < 8; j++) rhv[j] = g_rh[n0 + tx + j * 16];

    float rowsum[8];
#pragma unroll
    for (int i = 0; i < 8; i++) {
        float s = 0.f;
#pragma unroll
        for (int j = 0; j < 8; j++) {
            float a = acc[i][j];
            s += a * a * a * rhv[j];   // sign(a)*|a|^3 == a^3
        }
        rowsum[i] = s;
    }

    // Reduce across the 16 tx lanes (lanes 0-15 / 16-31 share ty)
#pragma unroll
    for (int off = 8; off >= 1; off >>= 1) {
#pragma unroll
        for (int i = 0; i < 8; i++)
            rowsum[i] += __shfl_xor_sync(0xffffffffu, rowsum[i], off);
    }
    if (tx == 0) {
#pragma unroll
        for (int i = 0; i < 8; i++)
            g_partial[(size_t)blockIdx.y * BQ + (m0 + ty + i * 16)] = rowsum[i];
    }
}

// ---------------------------------------------------------------------------
// Kernel 5: reduce partials over the 157 n-blocks, write logits + sigmoid.
// ---------------------------------------------------------------------------
__global__ void reduce_kernel(float* __restrict__ out, int out_size)
{
    int b = blockIdx.x * blockDim.x + threadIdx.x;
    if (b >= BQ) return;
    float s = 0.f;
    for (int j = 0; j < NB_N; j++) s += g_partial[(size_t)j * BQ + b];
    if (b < out_size) out[b] = s;                               // logits
    if (BQ + b < out_size) out[BQ + b] = 1.f / (1.f + expf(-s)); // preds
}

// ---------------------------------------------------------------------------
extern "C" void kernel_launch(void* const* d_in, const int* in_sizes, int n_in,
                              void* d_out, int out_size)
{
    const float* X   = (const float*)d_in[0];  // [4096,768]
    const float* D   = (const float*)d_in[1];  // [20000,768]
    const float* r   = (const float*)d_in[2];  // [20000,1]
    const float* g_w = (const float*)d_in[3];  // [512,768]
    const float* g_b = (const float*)d_in[4];  // [512]
    const float* h_w = (const float*)d_in[5];  // [1,1]
    const float* h_b = (const float*)d_in[6];  // [1]
    float* out = (float*)d_out;

    dim3 g1(TOTROWS / 128, EDIM / 128);        // (189, 4)
    embed_gemm_kernel<<<g1, 256>>>(X, D, g_w, g_b);

    normalize_kernel<<<REALROWS, 128>>>();

    rh_kernel<<<(NEX + 255) / 256, 256>>>(r, h_w, h_b);

    dim3 g4(NB_M, NB_N);                       // (32, 157)
    minerva_main_kernel<<<g4, 256>>>();

    reduce_kernel<<<(BQ + 127) / 128, 128>>>(out, out_size);
}

// round 3
// speedup vs baseline: 2.1535x; 2.1535x over previous
#include <cuda_runtime.h>
#include <cuda_bf16.h>
#include <stdint.h>
#include <math.h>

// ---------------- problem dims ----------------
#define BQ       4096
#define NEX      20000
#define NPAD     20096               // 157 * 128
#define FDIM     768
#define EDIM     512
#define TOTROWS  (BQ + NPAD)         // 24192 = 189*128
#define REALROWS (BQ + NEX)          // 24096
#define NBN      157

// ---------------- scratch (.bss, zero-initialized at load) ----------------
__device__ float         g_XDe[(size_t)TOTROWS * EDIM];  // fp32 embeds (pre-norm)
__device__ __nv_bfloat16 g_hi[(size_t)TOTROWS * EDIM];   // normalized, bf16 hi
__device__ __nv_bfloat16 g_lo[(size_t)TOTROWS * EDIM];   // normalized, bf16 lo
__device__ float         g_rh[NPAD];                      // pad stays 0
__device__ float         g_partial[NBN * BQ];

// ---------------- warp-mma helpers (base-target instructions only) --------
__device__ __forceinline__ void ldsm4(uint32_t& r0, uint32_t& r1,
                                      uint32_t& r2, uint32_t& r3, uint32_t addr) {
    asm volatile("ldmatrix.sync.aligned.m8n8.x4.shared.b16 {%0,%1,%2,%3}, [%4];"
                 : "=r"(r0), "=r"(r1), "=r"(r2), "=r"(r3) : "r"(addr));
}

__device__ __forceinline__ void mma_bf16(float* c, const uint32_t* a,
                                         uint32_t b0, uint32_t b1) {
    asm volatile(
        "mma.sync.aligned.m16n8k16.row.col.f32.bf16.bf16.f32 "
        "{%0,%1,%2,%3},{%4,%5,%6,%7},{%8,%9},{%0,%1,%2,%3};"
        : "+f"(c[0]), "+f"(c[1]), "+f"(c[2]), "+f"(c[3])
        : "r"(a[0]), "r"(a[1]), "r"(a[2]), "r"(a[3]), "r"(b0), "r"(b1));
}

__device__ __forceinline__ void cp16(uint32_t dst, const void* src) {
    asm volatile("cp.async.cg.shared.global [%0], [%1], 16;"
                 :: "r"(dst), "l"(src) : "memory");
}

// ---------------------------------------------------------------------------
// Embed GEMM: C[row,e] = sum_f A[row,f]*g_w[e,f] + g_b[e]; A=[X;D].
// 3-pass bf16 split, on-the-fly conversion. CTA 128x128, BK=32, 8 warps.
// ---------------------------------------------------------------------------
__global__ __launch_bounds__(256, 1) void embed_gemm_kernel(
    const float* __restrict__ X, const float* __restrict__ D,
    const float* __restrict__ Wg, const float* __restrict__ Bb)
{
    __shared__ float sbias[128];
    __shared__ __align__(16) __nv_bfloat16 sA[2][128 * 40];  // [comp][row*40+k]
    __shared__ __align__(16) __nv_bfloat16 sB[2][128 * 40];

    const int tid = threadIdx.x;
    const int wid = tid >> 5, lane = tid & 31;
    const int wm = wid & 3, wn = wid >> 2;          // warp tile 32(m) x 64(n)
    const int m0 = blockIdx.x * 128, n0 = blockIdx.y * 128;

    const uint32_t sa_u = (uint32_t)__cvta_generic_to_shared(&sA[0][0]);
    const uint32_t sb_u = (uint32_t)__cvta_generic_to_shared(&sB[0][0]);

    if (tid < 128) sbias[tid] = Bb[n0 + tid];

    float facc[2][8][4];
#pragma unroll
    for (int mt = 0; mt < 2; mt++)
#pragma unroll
        for (int nt = 0; nt < 8; nt++)
#pragma unroll
            for (int i = 0; i < 4; i++) facc[mt][nt][i] = 0.f;

    for (int chunk = 0; chunk < FDIM / 32; chunk++) {
        const int k0 = chunk * 32;
        float av[16], bv[16];
#pragma unroll
        for (int t = 0; t < 16; t++) {
            int idx = tid + t * 256;
            int row = idx >> 5, k = idx & 31;
            int gr = m0 + row;
            float a = 0.f;
            if (gr < BQ)            a = X[(size_t)gr * FDIM + k0 + k];
            else if (gr < REALROWS) a = D[(size_t)(gr - BQ) * FDIM + k0 + k];
            av[t] = a;
            bv[t] = Wg[(size_t)(n0 + row) * FDIM + k0 + k];
        }
        __syncthreads();
#pragma unroll
        for (int t = 0; t < 16; t++) {
            int idx = tid + t * 256;
            int row = idx >> 5, k = idx & 31;
            __nv_bfloat16 ah = __float2bfloat16(av[t]);
            sA[0][row * 40 + k] = ah;
            sA[1][row * 40 + k] = __float2bfloat16(av[t] - __bfloat162float(ah));
            __nv_bfloat16 bh = __float2bfloat16(bv[t]);
            sB[0][row * 40 + k] = bh;
            sB[1][row * 40 + k] = __float2bfloat16(bv[t] - __bfloat162float(bh));
        }
        __syncthreads();

#pragma unroll
        for (int ks = 0; ks < 2; ks++) {
            const int koff = ks * 16 + (lane >> 4) * 8;
            uint32_t a[2][2][4];
#pragma unroll
            for (int comp = 0; comp < 2; comp++)
#pragma unroll
                for (int mt = 0; mt < 2; mt++) {
                    int row = wm * 32 + mt * 16 + (lane & 15);
                    ldsm4(a[comp][mt][0], a[comp][mt][1], a[comp][mt][2], a[comp][mt][3],
                          sa_u + comp * 10240 + row * 80 + koff * 2);
                }
            uint32_t b[2][4][4];
#pragma unroll
            for (int comp = 0; comp < 2; comp++)
#pragma unroll
                for (int ng = 0; ng < 4; ng++) {
                    int nr = wn * 64 + ng * 16 + (lane & 15);
                    ldsm4(b[comp][ng][0], b[comp][ng][1], b[comp][ng][2], b[comp][ng][3],
                          sb_u + comp * 10240 + nr * 80 + koff * 2);
                }
#pragma unroll
            for (int mt = 0; mt < 2; mt++)
#pragma unroll
                for (int ng = 0; ng < 4; ng++)
#pragma unroll
                    for (int h = 0; h < 2; h++) {
                        float* c = facc[mt][ng * 2 + h];
                        mma_bf16(c, a[0][mt], b[0][ng][h], b[0][ng][2 + h]); // hi*hi
                        mma_bf16(c, a[0][mt], b[1][ng][h], b[1][ng][2 + h]); // hi*lo
                        mma_bf16(c, a[1][mt], b[0][ng][h], b[0][ng][2 + h]); // lo*hi
                    }
        }
        __syncthreads();
    }

    // epilogue: +bias, store fp32
#pragma unroll
    for (int mt = 0; mt < 2; mt++)
#pragma unroll
        for (int nt = 0; nt < 8; nt++)
#pragma unroll
            for (int p = 0; p < 2; p++) {           // p = (i>>1)
                int row = m0 + wm * 32 + mt * 16 + p * 8 + (lane >> 2);
                if (row >= REALROWS) continue;
                int cl = wn * 64 + nt * 8 + (lane & 3) * 2;
                float2 v;
                v.x = facc[mt][nt][p * 2 + 0] + sbias[cl];
                v.y = facc[mt][nt][p * 2 + 1] + sbias[cl + 1];
                *(float2*)&g_XDe[(size_t)row * EDIM + n0 + cl] = v;
            }
}

// ---------------------------------------------------------------------------
// Normalize rows, emit bf16 hi/lo
// ---------------------------------------------------------------------------
__global__ __launch_bounds__(128) void normalize_kernel()
{
    const int row = blockIdx.x;
    const float* p = g_XDe + (size_t)row * EDIM;
    const int t = threadIdx.x;
    float v[4];
    float ss = 0.f;
#pragma unroll
    for (int i = 0; i < 4; i++) { v[i] = p[t + i * 128]; ss += v[i] * v[i]; }
#pragma unroll
    for (int off = 16; off >= 1; off >>= 1)
        ss += __shfl_xor_sync(0xffffffffu, ss, off);
    __shared__ float red[4];
    if ((t & 31) == 0) red[t >> 5] = ss;
    __syncthreads();
    float inv = 1.f / fmaxf(sqrtf(red[0] + red[1] + red[2] + red[3]), 1e-12f);
#pragma unroll
    for (int i = 0; i < 4; i++) {
        float nv = v[i] * inv;
        __nv_bfloat16 h = __float2bfloat16(nv);
        g_hi[(size_t)row * EDIM + t + i * 128] = h;
        g_lo[(size_t)row * EDIM + t + i * 128] =
            __float2bfloat16(nv - __bfloat162float(h));
    }
}

__global__ void rh_kernel(const float* __restrict__ r,
                          const float* __restrict__ h_w,
                          const float* __restrict__ h_b)
{
    int n = blockIdx.x * blockDim.x + threadIdx.x;
    if (n < NEX) g_rh[n] = (2.f * r[n] - 1.f) * h_w[0] + h_b[0];
}

// ---------------------------------------------------------------------------
// Main GEMM: a = Xen . Den^T (K=512), fused cube*rh + n-reduce.
// cp.async double-buffered, 3-pass bf16. CTA 128x128.
// SMEM: [0,512) rh tile; stages at 512: per stage {Ahi,Alo,Bhi,Blo} x 10240B.
// ---------------------------------------------------------------------------
#define MSTG 40960
#define SMEM_MAIN (512 + 2 * MSTG)

__global__ __launch_bounds__(256, 1) void minerva_main_kernel()
{
    extern __shared__ char smem[];
    const uint32_t smem_u = (uint32_t)__cvta_generic_to_shared(smem);
    float* rhs = (float*)smem;

    const int tid = threadIdx.x;
    const int wid = tid >> 5, lane = tid & 31;
    const int wm = wid & 3, wn = wid >> 2;
    const int m0 = blockIdx.x * 128, n0 = blockIdx.y * 128;

    if (tid < 128) rhs[tid] = g_rh[n0 + tid];

    const __nv_bfloat16* Ahi = g_hi;                          // query rows
    const __nv_bfloat16* Alo = g_lo;
    const __nv_bfloat16* Bhi = g_hi + (size_t)BQ * EDIM;      // exemplar rows
    const __nv_bfloat16* Blo = g_lo + (size_t)BQ * EDIM;

    auto issue_load = [&](int chunk, int s) {
        const int k0 = chunk * 32;
        const uint32_t st = smem_u + 512 + s * MSTG;
        const int idx0 = tid, idx1 = tid + 256;
#pragma unroll
        for (int t = 0; t < 2; t++) {
            int idx = t ? idx1 : idx0;          // [0,512)
            int row = idx >> 2, seg = idx & 3;
            size_t aofs = (size_t)(m0 + row) * EDIM + k0 + seg * 8;
            size_t bofs = (size_t)(n0 + row) * EDIM + k0 + seg * 8;
            uint32_t d = row * 80 + seg * 16;
            cp16(st + d,                 Ahi + aofs);
            cp16(st + 10240 + d,         Alo + aofs);
            cp16(st + 20480 + d,         Bhi + bofs);
            cp16(st + 30720 + d,         Blo + bofs);
        }
        asm volatile("cp.async.commit_group;" ::: "memory");
    };

    float facc[2][8][4];
#pragma unroll
    for (int mt = 0; mt < 2; mt++)
#pragma unroll
        for (int nt = 0; nt < 8; nt++)
#pragma unroll
            for (int i = 0; i < 4; i++) facc[mt][nt][i] = 0.f;

    issue_load(0, 0);

    for (int chunk = 0; chunk < EDIM / 32; chunk++) {
        const int s = chunk & 1;
        if (chunk + 1 < EDIM / 32) {
            issue_load(chunk + 1, s ^ 1);
            asm volatile("cp.async.wait_group 1;" ::: "memory");
        } else {
            asm volatile("cp.async.wait_group 0;" ::: "memory");
        }
        __syncthreads();

        const uint32_t st = smem_u + 512 + s * MSTG;
#pragma unroll
        for (int ks = 0; ks < 2; ks++) {
            const int koff = ks * 16 + (lane >> 4) * 8;
            uint32_t a[2][2][4];
#pragma unroll
            for (int comp = 0; comp < 2; comp++)
#pragma unroll
                for (int mt = 0; mt < 2; mt++) {
                    int row = wm * 32 + mt * 16 + (lane & 15);
                    ldsm4(a[comp][mt][0], a[comp][mt][1], a[comp][mt][2], a[comp][mt][3],
                          st + comp * 10240 + row * 80 + koff * 2);
                }
            uint32_t b[2][4][4];
#pragma unroll
            for (int comp = 0; comp < 2; comp++)
#pragma unroll
                for (int ng = 0; ng < 4; ng++) {
                    int nr = wn * 64 + ng * 16 + (lane & 15);
                    ldsm4(b[comp][ng][0], b[comp][ng][1], b[comp][ng][2], b[comp][ng][3],
                          st + 20480 + comp * 10240 + nr * 80 + koff * 2);
                }
#pragma unroll
            for (int mt = 0; mt < 2; mt++)
#pragma unroll
                for (int ng = 0; ng < 4; ng++)
#pragma unroll
                    for (int h = 0; h < 2; h++) {
                        float* c = facc[mt][ng * 2 + h];
                        mma_bf16(c, a[0][mt], b[0][ng][h], b[0][ng][2 + h]);
                        mma_bf16(c, a[0][mt], b[1][ng][h], b[1][ng][2 + h]);
                        mma_bf16(c, a[1][mt], b[0][ng][h], b[0][ng][2 + h]);
                    }
        }
        __syncthreads();
    }

    // epilogue: cube * rh, reduce over n
    float rsum[4] = {0.f, 0.f, 0.f, 0.f};
#pragma unroll
    for (int mt = 0; mt < 2; mt++)
#pragma unroll
        for (int nt = 0; nt < 8; nt++)
#pragma unroll
            for (int i = 0; i < 4; i++) {
                int cl = wn * 64 + nt * 8 + (lane & 3) * 2 + (i & 1);
                float a = facc[mt][nt][i];
                rsum[mt * 2 + (i >> 1)] += a * a * a * rhs[cl];
            }
#pragma unroll
    for (int off = 1; off <= 2; off <<= 1)
#pragma unroll
        for (int k = 0; k < 4; k++)
            rsum[k] += __shfl_xor_sync(0xffffffffu, rsum[k], off);

    float* red = (float*)(smem + 512);   // 256 floats; stages are dead now
    if ((lane & 3) == 0) {
#pragma unroll
        for (int mt = 0; mt < 2; mt++)
#pragma unroll
            for (int h = 0; h < 2; h++)
                red[wn * 128 + wm * 32 + mt * 16 + h * 8 + (lane >> 2)] =
                    rsum[mt * 2 + h];
    }
    __syncthreads();
    if (tid < 128)
        g_partial[(size_t)blockIdx.y * BQ + m0 + tid] = red[tid] + red[128 + tid];
}

// ---------------------------------------------------------------------------
__global__ void reduce_kernel(float* __restrict__ out, int out_size)
{
    int b = blockIdx.x * blockDim.x + threadIdx.x;
    if (b >= BQ) return;
    float s = 0.f;
#pragma unroll 4
    for (int j = 0; j < NBN; j++) s += g_partial[(size_t)j * BQ + b];
    if (b < out_size) out[b] = s;
    if (BQ + b < out_size) out[BQ + b] = 1.f / (1.f + expf(-s));
}

// ---------------------------------------------------------------------------
extern "C" void kernel_launch(void* const* d_in, const int* in_sizes, int n_in,
                              void* d_out, int out_size)
{
    const float* X   = (const float*)d_in[0];
    const float* D   = (const float*)d_in[1];
    const float* r   = (const float*)d_in[2];
    const float* g_w = (const float*)d_in[3];
    const float* g_b = (const float*)d_in[4];
    const float* h_w = (const float*)d_in[5];
    const float* h_b = (const float*)d_in[6];
    float* out = (float*)d_out;

    cudaFuncSetAttribute(minerva_main_kernel,
                         cudaFuncAttributeMaxDynamicSharedMemorySize, SMEM_MAIN);

    dim3 ge(TOTROWS / 128, EDIM / 128);        // (189, 4)
    embed_gemm_kernel<<<ge, 256>>>(X, D, g_w, g_b);

    normalize_kernel<<<REALROWS, 128>>>();

    rh_kernel<<<(NEX + 255) / 256, 256>>>(r, h_w, h_b);

    dim3 gm(BQ / 128, NPAD / 128);             // (32, 157)
    minerva_main_kernel<<<gm, 256, SMEM_MAIN>>>();

    reduce_kernel<<<(BQ + 127) / 128, 128>>>(out, out_size);
}

// round 4
// speedup vs baseline: 2.7124x; 1.2595x over previous
#include <cuda_runtime.h>
#include <cuda_bf16.h>
#include <stdint.h>
#include <math.h>

// ---------------- problem dims ----------------
#define BQ       4096
#define NEX      20000
#define NPAD     20096               // 157 * 128
#define FDIM     768
#define EDIM     512
#define TOTROWS  (BQ + NPAD)         // 24192 = 189*128
#define REALROWS (BQ + NEX)          // 24096
#define NBN      157

// ---------------- scratch (.bss, zero-init at load; pads stay 0) ----------
__device__ float         g_XDe[(size_t)TOTROWS * EDIM];   // fp32 embeds (pre-norm)
__device__ __nv_bfloat16 g_fhi[(size_t)TOTROWS * FDIM];   // [X;D] features hi
__device__ __nv_bfloat16 g_flo[(size_t)TOTROWS * FDIM];   // [X;D] features lo
__device__ __nv_bfloat16 g_whi[(size_t)EDIM * FDIM];      // g_w hi
__device__ __nv_bfloat16 g_wlo[(size_t)EDIM * FDIM];      // g_w lo
__device__ __nv_bfloat16 g_hi[(size_t)TOTROWS * EDIM];    // normalized embeds hi
__device__ __nv_bfloat16 g_lo[(size_t)TOTROWS * EDIM];    // normalized embeds lo
__device__ float         g_rh[NPAD];
__device__ float         g_partial[NBN * BQ];

// ---------------- helpers (base-target instructions only) ----------------
__device__ __forceinline__ void ldsm4(uint32_t& r0, uint32_t& r1,
                                      uint32_t& r2, uint32_t& r3, uint32_t addr) {
    asm volatile("ldmatrix.sync.aligned.m8n8.x4.shared.b16 {%0,%1,%2,%3}, [%4];"
                 : "=r"(r0), "=r"(r1), "=r"(r2), "=r"(r3) : "r"(addr));
}
__device__ __forceinline__ void mma_bf16(float* c, const uint32_t* a,
                                         uint32_t b0, uint32_t b1) {
    asm volatile(
        "mma.sync.aligned.m16n8k16.row.col.f32.bf16.bf16.f32 "
        "{%0,%1,%2,%3},{%4,%5,%6,%7},{%8,%9},{%0,%1,%2,%3};"
        : "+f"(c[0]), "+f"(c[1]), "+f"(c[2]), "+f"(c[3])
        : "r"(a[0]), "r"(a[1]), "r"(a[2]), "r"(a[3]), "r"(b0), "r"(b1));
}
__device__ __forceinline__ void cp16(uint32_t dst, const void* src) {
    asm volatile("cp.async.cg.shared.global [%0], [%1], 16;"
                 :: "r"(dst), "l"(src) : "memory");
}

// ---------------------------------------------------------------------------
// Unified 3-pass bf16-split GEMM, cp.async double-buffered.
// MODE 0 (embed): A=g_fhi/lo [TOTROWS x 768], B=g_whi/lo [512 x 768],
//                 epilogue: +bias(coef_in), store fp32 to g_XDe.
// MODE 1 (main) : A=g_hi/lo query rows, B=g_hi/lo exemplar rows (K=512),
//                 epilogue: cube * g_rh, reduce over n -> g_partial.
// CTA 128x128, 8 warps (32m x 64n each), BK=32.
// SMEM: [0,512) coef; stages at 512: {Ahi,Alo,Bhi,Blo} x 10240B each.
// ---------------------------------------------------------------------------
#define MSTG 40960
#define SMEM_GEMM (512 + 2 * MSTG)   // 82432

template <int MODE>
__global__ __launch_bounds__(256, 2) void gemm_kernel(const float* __restrict__ coef_in)
{
    constexpr int K = (MODE == 0) ? FDIM : EDIM;
    constexpr int NK = K / 32;

    extern __shared__ char smem[];
    const uint32_t smem_u = (uint32_t)__cvta_generic_to_shared(smem);
    float* scoef = (float*)smem;

    const int tid = threadIdx.x;
    const int wid = tid >> 5, lane = tid & 31;
    const int wm = wid & 3, wn = wid >> 2;
    const int m0 = blockIdx.x * 128, n0 = blockIdx.y * 128;

    const __nv_bfloat16 *Ah, *Al, *Bh, *Bl;
    if (MODE == 0) {
        Ah = g_fhi; Al = g_flo; Bh = g_whi; Bl = g_wlo;
    } else {
        Ah = g_hi; Al = g_lo;
        Bh = g_hi + (size_t)BQ * EDIM; Bl = g_lo + (size_t)BQ * EDIM;
    }

    if (tid < 128)
        scoef[tid] = (MODE == 0) ? coef_in[n0 + tid] : g_rh[n0 + tid];

    auto issue_load = [&](int chunk, int s) {
        const int k0 = chunk * 32;
        const uint32_t st = smem_u + 512 + s * MSTG;
#pragma unroll
        for (int t = 0; t < 2; t++) {
            int idx = tid + t * 256;            // [0,512)
            int row = idx >> 2, seg = idx & 3;
            size_t aofs = (size_t)(m0 + row) * K + k0 + seg * 8;
            size_t bofs = (size_t)(n0 + row) * K + k0 + seg * 8;
            uint32_t d = row * 80 + seg * 16;
            cp16(st + d,         Ah + aofs);
            cp16(st + 10240 + d, Al + aofs);
            cp16(st + 20480 + d, Bh + bofs);
            cp16(st + 30720 + d, Bl + bofs);
        }
        asm volatile("cp.async.commit_group;" ::: "memory");
    };

    float facc[2][8][4];
#pragma unroll
    for (int mt = 0; mt < 2; mt++)
#pragma unroll
        for (int nt = 0; nt < 8; nt++)
#pragma unroll
            for (int i = 0; i < 4; i++) facc[mt][nt][i] = 0.f;

    issue_load(0, 0);

    for (int chunk = 0; chunk < NK; chunk++) {
        const int s = chunk & 1;
        if (chunk + 1 < NK) {
            issue_load(chunk + 1, s ^ 1);
            asm volatile("cp.async.wait_group 1;" ::: "memory");
        } else {
            asm volatile("cp.async.wait_group 0;" ::: "memory");
        }
        __syncthreads();

        const uint32_t st = smem_u + 512 + s * MSTG;
#pragma unroll
        for (int ks = 0; ks < 2; ks++) {
            const int koff2 = (ks * 16 + (lane >> 4) * 8) * 2;
            uint32_t a[2][2][4];
#pragma unroll
            for (int comp = 0; comp < 2; comp++)
#pragma unroll
                for (int mt = 0; mt < 2; mt++) {
                    int row = wm * 32 + mt * 16 + (lane & 15);
                    ldsm4(a[comp][mt][0], a[comp][mt][1], a[comp][mt][2], a[comp][mt][3],
                          st + comp * 10240 + row * 80 + koff2);
                }
#pragma unroll
            for (int ng = 0; ng < 4; ng++) {
                int nr = wn * 64 + ng * 16 + (lane & 15);
                uint32_t bh4[4], bl4[4];
                ldsm4(bh4[0], bh4[1], bh4[2], bh4[3], st + 20480 + nr * 80 + koff2);
                ldsm4(bl4[0], bl4[1], bl4[2], bl4[3], st + 30720 + nr * 80 + koff2);
#pragma unroll
                for (int mt = 0; mt < 2; mt++)
#pragma unroll
                    for (int h = 0; h < 2; h++) {
                        float* c = facc[mt][ng * 2 + h];
                        mma_bf16(c, a[0][mt], bh4[h], bh4[2 + h]);  // hi*hi
                        mma_bf16(c, a[0][mt], bl4[h], bl4[2 + h]);  // hi*lo
                        mma_bf16(c, a[1][mt], bh4[h], bh4[2 + h]);  // lo*hi
                    }
            }
        }
        __syncthreads();
    }

    if (MODE == 0) {
        // +bias, store fp32
#pragma unroll
        for (int mt = 0; mt < 2; mt++)
#pragma unroll
            for (int nt = 0; nt < 8; nt++)
#pragma unroll
                for (int p = 0; p < 2; p++) {
                    int row = m0 + wm * 32 + mt * 16 + p * 8 + (lane >> 2);
                    if (row >= REALROWS) continue;
                    int cl = wn * 64 + nt * 8 + (lane & 3) * 2;
                    float2 v;
                    v.x = facc[mt][nt][p * 2 + 0] + scoef[cl];
                    v.y = facc[mt][nt][p * 2 + 1] + scoef[cl + 1];
                    *(float2*)&g_XDe[(size_t)row * EDIM + n0 + cl] = v;
                }
    } else {
        // cube * rh, reduce over n
        float rsum[4] = {0.f, 0.f, 0.f, 0.f};
#pragma unroll
        for (int mt = 0; mt < 2; mt++)
#pragma unroll
            for (int nt = 0; nt < 8; nt++)
#pragma unroll
                for (int i = 0; i < 4; i++) {
                    int cl = wn * 64 + nt * 8 + (lane & 3) * 2 + (i & 1);
                    float a = facc[mt][nt][i];
                    rsum[mt * 2 + (i >> 1)] += a * a * a * scoef[cl];
                }
#pragma unroll
        for (int off = 1; off <= 2; off <<= 1)
#pragma unroll
            for (int k = 0; k < 4; k++)
                rsum[k] += __shfl_xor_sync(0xffffffffu, rsum[k], off);

        float* red = (float*)(smem + 512);  // stages dead now
        if ((lane & 3) == 0) {
#pragma unroll
            for (int mt = 0; mt < 2; mt++)
#pragma unroll
                for (int h = 0; h < 2; h++)
                    red[wn * 128 + wm * 32 + mt * 16 + h * 8 + (lane >> 2)] =
                        rsum[mt * 2 + h];
        }
        __syncthreads();
        if (tid < 128)
            g_partial[(size_t)blockIdx.y * BQ + m0 + tid] = red[tid] + red[128 + tid];
    }
}

// ---------------------------------------------------------------------------
// Convert fp32 -> bf16 hi/lo. DST 0: g_fhi/g_flo, DST 1: g_whi/g_wlo.
// ---------------------------------------------------------------------------
template <int DST>
__global__ void convert_kernel(const float* __restrict__ src, size_t dst_off, int n)
{
    __nv_bfloat16* dhi = (DST == 0) ? g_fhi : g_whi;
    __nv_bfloat16* dlo = (DST == 0) ? g_flo : g_wlo;
    int i = blockIdx.x * blockDim.x + threadIdx.x;
    int stride = gridDim.x * blockDim.x;
    for (; i < n; i += stride) {
        float v = src[i];
        __nv_bfloat16 h = __float2bfloat16(v);
        dhi[dst_off + i] = h;
        dlo[dst_off + i] = __float2bfloat16(v - __bfloat162float(h));
    }
}

// ---------------------------------------------------------------------------
__global__ __launch_bounds__(128) void normalize_kernel()
{
    const int row = blockIdx.x;
    const float* p = g_XDe + (size_t)row * EDIM;
    const int t = threadIdx.x;
    float v[4];
    float ss = 0.f;
#pragma unroll
    for (int i = 0; i < 4; i++) { v[i] = p[t + i * 128]; ss += v[i] * v[i]; }
#pragma unroll
    for (int off = 16; off >= 1; off >>= 1)
        ss += __shfl_xor_sync(0xffffffffu, ss, off);
    __shared__ float red[4];
    if ((t & 31) == 0) red[t >> 5] = ss;
    __syncthreads();
    float inv = 1.f / fmaxf(sqrtf(red[0] + red[1] + red[2] + red[3]), 1e-12f);
#pragma unroll
    for (int i = 0; i < 4; i++) {
        float nv = v[i] * inv;
        __nv_bfloat16 h = __float2bfloat16(nv);
        g_hi[(size_t)row * EDIM + t + i * 128] = h;
        g_lo[(size_t)row * EDIM + t + i * 128] =
            __float2bfloat16(nv - __bfloat162float(h));
    }
}

__global__ void rh_kernel(const float* __restrict__ r,
                          const float* __restrict__ h_w,
                          const float* __restrict__ h_b)
{
    int n = blockIdx.x * blockDim.x + threadIdx.x;
    if (n < NEX) g_rh[n] = (2.f * r[n] - 1.f) * h_w[0] + h_b[0];
}

__global__ void reduce_kernel(float* __restrict__ out, int out_size)
{
    int b = blockIdx.x * blockDim.x + threadIdx.x;
    if (b >= BQ) return;
    float s = 0.f;
#pragma unroll 4
    for (int j = 0; j < NBN; j++) s += g_partial[(size_t)j * BQ + b];
    if (b < out_size) out[b] = s;
    if (BQ + b < out_size) out[BQ + b] = 1.f / (1.f + expf(-s));
}

// ---------------------------------------------------------------------------
extern "C" void kernel_launch(void* const* d_in, const int* in_sizes, int n_in,
                              void* d_out, int out_size)
{
    const float* X   = (const float*)d_in[0];
    const float* D   = (const float*)d_in[1];
    const float* r   = (const float*)d_in[2];
    const float* g_w = (const float*)d_in[3];
    const float* g_b = (const float*)d_in[4];
    const float* h_w = (const float*)d_in[5];
    const float* h_b = (const float*)d_in[6];
    float* out = (float*)d_out;

    cudaFuncSetAttribute(gemm_kernel<0>,
                         cudaFuncAttributeMaxDynamicSharedMemorySize, SMEM_GEMM);
    cudaFuncSetAttribute(gemm_kernel<1>,
                         cudaFuncAttributeMaxDynamicSharedMemorySize, SMEM_GEMM);

    // split inputs to bf16 hi/lo
    convert_kernel<0><<<592, 256>>>(X, 0, BQ * FDIM);
    convert_kernel<0><<<592, 256>>>(D, (size_t)BQ * FDIM, NEX * FDIM);
    convert_kernel<1><<<296, 256>>>(g_w, 0, EDIM * FDIM);

    rh_kernel<<<(NEX + 255) / 256, 256>>>(r, h_w, h_b);

    // embed GEMM
    dim3 ge(TOTROWS / 128, EDIM / 128);        // (189, 4)
    gemm_kernel<0><<<ge, 256, SMEM_GEMM>>>(g_b);

    normalize_kernel<<<REALROWS, 128>>>();

    // main GEMM (fused cube*rh + n-reduction)
    dim3 gm(BQ / 128, NPAD / 128);             // (32, 157)
    gemm_kernel<1><<<gm, 256, SMEM_GEMM>>>(nullptr);

    reduce_kernel<<<(BQ + 127) / 128, 128>>>(out, out_size);
}

// round 5
// speedup vs baseline: 2.9495x; 1.0874x over previous
#include <cuda_runtime.h>
#include <cuda_bf16.h>
#include <stdint.h>
#include <math.h>

// ---------------- problem dims ----------------
#define BQ       4096
#define NEX      20000
#define NPAD     20096               // 157 * 128
#define FDIM     768
#define EDIM     512
#define TOTROWS  (BQ + NPAD)         // 24192 = 189*128
#define REALROWS (BQ + NEX)          // 24096
#define NBN      157

// ---------------- scratch (.bss, zero-init at load; pads stay 0) ----------
__device__ float         g_XDe[(size_t)TOTROWS * EDIM];   // fp32 embeds (pre-norm)
__device__ __nv_bfloat16 g_fhi[(size_t)TOTROWS * FDIM];   // [X;D] features hi
__device__ __nv_bfloat16 g_flo[(size_t)TOTROWS * FDIM];   // [X;D] features lo
__device__ __nv_bfloat16 g_whi[(size_t)EDIM * FDIM];      // g_w hi
__device__ __nv_bfloat16 g_wlo[(size_t)EDIM * FDIM];      // g_w lo
__device__ __nv_bfloat16 g_hi[(size_t)TOTROWS * EDIM];    // normalized embeds hi
__device__ __nv_bfloat16 g_lo[(size_t)TOTROWS * EDIM];    // normalized embeds lo
__device__ float         g_rh[NPAD];
__device__ float         g_partial[NBN * BQ];

// ---------------- helpers (base-target instructions only) ----------------
__device__ __forceinline__ void ldsm4(uint32_t& r0, uint32_t& r1,
                                      uint32_t& r2, uint32_t& r3, uint32_t addr) {
    asm volatile("ldmatrix.sync.aligned.m8n8.x4.shared.b16 {%0,%1,%2,%3}, [%4];"
                 : "=r"(r0), "=r"(r1), "=r"(r2), "=r"(r3) : "r"(addr));
}
__device__ __forceinline__ void mma_bf16(float* c, const uint32_t* a,
                                         uint32_t b0, uint32_t b1) {
    asm volatile(
        "mma.sync.aligned.m16n8k16.row.col.f32.bf16.bf16.f32 "
        "{%0,%1,%2,%3},{%4,%5,%6,%7},{%8,%9},{%0,%1,%2,%3};"
        : "+f"(c[0]), "+f"(c[1]), "+f"(c[2]), "+f"(c[3])
        : "r"(a[0]), "r"(a[1]), "r"(a[2]), "r"(a[3]), "r"(b0), "r"(b1));
}
__device__ __forceinline__ void cp16(uint32_t dst, const void* src) {
    asm volatile("cp.async.cg.shared.global [%0], [%1], 16;"
                 :: "r"(dst), "l"(src) : "memory");
}
// SW128 swizzle within a 16KB subtile of 128B rows
#define SW(b) ((b) ^ (((b) >> 3) & 0x70))

// ---------------------------------------------------------------------------
// Unified 3-pass bf16-split GEMM, 3-stage cp.async pipeline, 1 sync/chunk.
// CTA 128x128, 8 warps (32m x 64n), BK=32.
// SMEM: [0,512) coef; stage s at 512 + s*32768:
//   A subtile [0,16384): row*128 + {hi: k*2 | lo: 64+k*2}, SW128-swizzled
//   B subtile [16384,32768): same
// ---------------------------------------------------------------------------
#define STG    32768
#define NSTAGE 3
#define SMEM_GEMM (512 + NSTAGE * STG)    // 98816

template <int MODE>
__global__ __launch_bounds__(256, 2) void gemm_kernel(const float* __restrict__ coef_in)
{
    constexpr int K = (MODE == 0) ? FDIM : EDIM;
    constexpr int NK = K / 32;

    extern __shared__ char smem[];
    const uint32_t smem_u = (uint32_t)__cvta_generic_to_shared(smem);
    float* scoef = (float*)smem;

    const int tid = threadIdx.x;
    const int wid = tid >> 5, lane = tid & 31;
    const int wm = wid & 3, wn = wid >> 2;
    const int m0 = blockIdx.x * 128, n0 = blockIdx.y * 128;

    const __nv_bfloat16 *Ah, *Al, *Bh, *Bl;
    if (MODE == 0) {
        Ah = g_fhi; Al = g_flo; Bh = g_whi; Bl = g_wlo;
    } else {
        Ah = g_hi; Al = g_lo;
        Bh = g_hi + (size_t)BQ * EDIM; Bl = g_lo + (size_t)BQ * EDIM;
    }

    if (tid < 128)
        scoef[tid] = (MODE == 0) ? coef_in[n0 + tid] : g_rh[n0 + tid];

    // 8 x 16B segments per thread per stage (2048 segs total)
    auto issue_load = [&](int chunk, int s) {
        const int k0 = chunk * 32;
        const uint32_t st = smem_u + 512 + s * STG;
#pragma unroll
        for (int t = 0; t < 8; t++) {
            int idx = t * 256 + tid;                // [0,2048)
            int mat = idx >> 10;                    // 0=A, 1=B
            int rid = (idx & 1023) >> 3;            // row 0..127
            int seg = idx & 7;                      // 0-3 hi, 4-7 lo
            int comp = seg >> 2, ks8 = seg & 3;
            size_t gofs = (size_t)((mat ? n0 : m0) + rid) * K + k0 + ks8 * 8;
            const __nv_bfloat16* src =
                mat ? (comp ? Bl : Bh) : (comp ? Al : Ah);
            uint32_t d = SW((uint32_t)(rid * 128 + seg * 16));
            cp16(st + mat * 16384 + d, src + gofs);
        }
        asm volatile("cp.async.commit_group;" ::: "memory");
    };

    float facc[2][8][4];
#pragma unroll
    for (int mt = 0; mt < 2; mt++)
#pragma unroll
        for (int nt = 0; nt < 8; nt++)
#pragma unroll
            for (int i = 0; i < 4; i++) facc[mt][nt][i] = 0.f;

    issue_load(0, 0);
    issue_load(1, 1);

    int s = 0;
    for (int chunk = 0; chunk < NK; chunk++) {
        if (chunk + 1 < NK) {
            asm volatile("cp.async.wait_group 1;" ::: "memory");
        } else {
            asm volatile("cp.async.wait_group 0;" ::: "memory");
        }
        __syncthreads();   // stage s ready; all warps done with stage (s+2)%3

        if (chunk + 2 < NK) issue_load(chunk + 2, (s + 2) % NSTAGE);

        const uint32_t st = smem_u + 512 + s * STG;
#pragma unroll
        for (int ks = 0; ks < 2; ks++) {
            const uint32_t kb = (uint32_t)(ks * 32 + (lane >> 4) * 16);
            uint32_t a[2][2][4];
#pragma unroll
            for (int comp = 0; comp < 2; comp++)
#pragma unroll
                for (int mt = 0; mt < 2; mt++) {
                    uint32_t row = wm * 32 + mt * 16 + (lane & 15);
                    ldsm4(a[comp][mt][0], a[comp][mt][1], a[comp][mt][2], a[comp][mt][3],
                          st + SW(row * 128 + comp * 64 + kb));
                }
#pragma unroll
            for (int ng = 0; ng < 4; ng++) {
                uint32_t nr = wn * 64 + ng * 16 + (lane & 15);
                uint32_t bh4[4], bl4[4];
                ldsm4(bh4[0], bh4[1], bh4[2], bh4[3],
                      st + 16384 + SW(nr * 128 + kb));
                ldsm4(bl4[0], bl4[1], bl4[2], bl4[3],
                      st + 16384 + SW(nr * 128 + 64 + kb));
#pragma unroll
                for (int mt = 0; mt < 2; mt++)
#pragma unroll
                    for (int h = 0; h < 2; h++) {
                        float* c = facc[mt][ng * 2 + h];
                        mma_bf16(c, a[0][mt], bh4[h], bh4[2 + h]);  // hi*hi
                        mma_bf16(c, a[0][mt], bl4[h], bl4[2 + h]);  // hi*lo
                        mma_bf16(c, a[1][mt], bh4[h], bh4[2 + h]);  // lo*hi
                    }
            }
        }
        s = (s + 1) % NSTAGE;
    }

    if (MODE == 0) {
        // +bias, store fp32
#pragma unroll
        for (int mt = 0; mt < 2; mt++)
#pragma unroll
            for (int nt = 0; nt < 8; nt++)
#pragma unroll
                for (int p = 0; p < 2; p++) {
                    int row = m0 + wm * 32 + mt * 16 + p * 8 + (lane >> 2);
                    if (row >= REALROWS) continue;
                    int cl = wn * 64 + nt * 8 + (lane & 3) * 2;
                    float2 v;
                    v.x = facc[mt][nt][p * 2 + 0] + scoef[cl];
                    v.y = facc[mt][nt][p * 2 + 1] + scoef[cl + 1];
                    *(float2*)&g_XDe[(size_t)row * EDIM + n0 + cl] = v;
                }
    } else {
        // cube * rh, reduce over n
        float rsum[4] = {0.f, 0.f, 0.f, 0.f};
#pragma unroll
        for (int mt = 0; mt < 2; mt++)
#pragma unroll
            for (int nt = 0; nt < 8; nt++)
#pragma unroll
                for (int i = 0; i < 4; i++) {
                    int cl = wn * 64 + nt * 8 + (lane & 3) * 2 + (i & 1);
                    float a = facc[mt][nt][i];
                    rsum[mt * 2 + (i >> 1)] += a * a * a * scoef[cl];
                }
#pragma unroll
        for (int off = 1; off <= 2; off <<= 1)
#pragma unroll
            for (int k = 0; k < 4; k++)
                rsum[k] += __shfl_xor_sync(0xffffffffu, rsum[k], off);

        __syncthreads();                       // stages dead after this
        float* red = (float*)(smem + 512);
        if ((lane & 3) == 0) {
#pragma unroll
            for (int mt = 0; mt < 2; mt++)
#pragma unroll
                for (int h = 0; h < 2; h++)
                    red[wn * 128 + wm * 32 + mt * 16 + h * 8 + (lane >> 2)] =
                        rsum[mt * 2 + h];
        }
        __syncthreads();
        if (tid < 128)
            g_partial[(size_t)blockIdx.y * BQ + m0 + tid] = red[tid] + red[128 + tid];
    }
}

// ---------------------------------------------------------------------------
template <int DST>
__global__ void convert_kernel(const float* __restrict__ src, size_t dst_off, int n)
{
    __nv_bfloat16* dhi = (DST == 0) ? g_fhi : g_whi;
    __nv_bfloat16* dlo = (DST == 0) ? g_flo : g_wlo;
    int i = blockIdx.x * blockDim.x + threadIdx.x;
    int stride = gridDim.x * blockDim.x;
    for (; i < n; i += stride) {
        float v = src[i];
        __nv_bfloat16 h = __float2bfloat16(v);
        dhi[dst_off + i] = h;
        dlo[dst_off + i] = __float2bfloat16(v - __bfloat162float(h));
    }
}

__global__ __launch_bounds__(128) void normalize_kernel()
{
    const int row = blockIdx.x;
    const float* p = g_XDe + (size_t)row * EDIM;
    const int t = threadIdx.x;
    float v[4];
    float ss = 0.f;
#pragma unroll
    for (int i = 0; i < 4; i++) { v[i] = p[t + i * 128]; ss += v[i] * v[i]; }
#pragma unroll
    for (int off = 16; off >= 1; off >>= 1)
        ss += __shfl_xor_sync(0xffffffffu, ss, off);
    __shared__ float red[4];
    if ((t & 31) == 0) red[t >> 5] = ss;
    __syncthreads();
    float inv = 1.f / fmaxf(sqrtf(red[0] + red[1] + red[2] + red[3]), 1e-12f);
#pragma unroll
    for (int i = 0; i < 4; i++) {
        float nv = v[i] * inv;
        __nv_bfloat16 h = __float2bfloat16(nv);
        g_hi[(size_t)row * EDIM + t + i * 128] = h;
        g_lo[(size_t)row * EDIM + t + i * 128] =
            __float2bfloat16(nv - __bfloat162float(h));
    }
}

__global__ void rh_kernel(const float* __restrict__ r,
                          const float* __restrict__ h_w,
                          const float* __restrict__ h_b)
{
    int n = blockIdx.x * blockDim.x + threadIdx.x;
    if (n < NEX) g_rh[n] = (2.f * r[n] - 1.f) * h_w[0] + h_b[0];
}

__global__ void reduce_kernel(float* __restrict__ out, int out_size)
{
    int b = blockIdx.x * blockDim.x + threadIdx.x;
    if (b >= BQ) return;
    float s = 0.f;
#pragma unroll 4
    for (int j = 0; j < NBN; j++) s += g_partial[(size_t)j * BQ + b];
    if (b < out_size) out[b] = s;
    if (BQ + b < out_size) out[BQ + b] = 1.f / (1.f + expf(-s));
}

// ---------------------------------------------------------------------------
extern "C" void kernel_launch(void* const* d_in, const int* in_sizes, int n_in,
                              void* d_out, int out_size)
{
    const float* X   = (const float*)d_in[0];
    const float* D   = (const float*)d_in[1];
    const float* r   = (const float*)d_in[2];
    const float* g_w = (const float*)d_in[3];
    const float* g_b = (const float*)d_in[4];
    const float* h_w = (const float*)d_in[5];
    const float* h_b = (const float*)d_in[6];
    float* out = (float*)d_out;

    cudaFuncSetAttribute(gemm_kernel<0>,
                         cudaFuncAttributeMaxDynamicSharedMemorySize, SMEM_GEMM);
    cudaFuncSetAttribute(gemm_kernel<1>,
                         cudaFuncAttributeMaxDynamicSharedMemorySize, SMEM_GEMM);

    convert_kernel<0><<<592, 256>>>(X, 0, BQ * FDIM);
    convert_kernel<0><<<592, 256>>>(D, (size_t)BQ * FDIM, NEX * FDIM);
    convert_kernel<1><<<296, 256>>>(g_w, 0, EDIM * FDIM);

    rh_kernel<<<(NEX + 255) / 256, 256>>>(r, h_w, h_b);

    dim3 ge(TOTROWS / 128, EDIM / 128);        // (189, 4)
    gemm_kernel<0><<<ge, 256, SMEM_GEMM>>>(g_b);

    normalize_kernel<<<REALROWS, 128>>>();

    dim3 gm(BQ / 128, NPAD / 128);             // (32, 157)
    gemm_kernel<1><<<gm, 256, SMEM_GEMM>>>(nullptr);

    reduce_kernel<<<(BQ + 127) / 128, 128>>>(out, out_size);
}

// round 6
// speedup vs baseline: 2.9957x; 1.0157x over previous
#include <cuda_runtime.h>
#include <cuda_bf16.h>
#include <stdint.h>
#include <math.h>

// ---------------- problem dims ----------------
#define BQ       4096
#define NEX      20000
#define NPAD     20096               // 157 * 128
#define FDIM     768
#define EDIM     512
#define TOTROWS  (BQ + NPAD)         // 24192 = 189*128
#define REALROWS (BQ + NEX)          // 24096
#define NBN      157

// ---------------- scratch (.bss, zero-init at load; pads stay 0) ----------
__device__ float         g_XDe[(size_t)TOTROWS * EDIM];   // fp32 embeds (pre-norm)
__device__ __nv_bfloat16 g_fhi[(size_t)TOTROWS * FDIM];   // [X;D] features hi
__device__ __nv_bfloat16 g_flo[(size_t)TOTROWS * FDIM];   // [X;D] features lo
__device__ __nv_bfloat16 g_whi[(size_t)EDIM * FDIM];      // g_w hi
__device__ __nv_bfloat16 g_wlo[(size_t)EDIM * FDIM];      // g_w lo
__device__ __nv_bfloat16 g_hi[(size_t)TOTROWS * EDIM];    // normalized embeds hi
__device__ __nv_bfloat16 g_lo[(size_t)TOTROWS * EDIM];    // normalized embeds lo
__device__ float         g_rh[NPAD];
__device__ float         g_partial[NBN * BQ];

// ---------------- helpers (base-target instructions only) ----------------
__device__ __forceinline__ void ldsm4(uint32_t& r0, uint32_t& r1,
                                      uint32_t& r2, uint32_t& r3, uint32_t addr) {
    asm volatile("ldmatrix.sync.aligned.m8n8.x4.shared.b16 {%0,%1,%2,%3}, [%4];"
                 : "=r"(r0), "=r"(r1), "=r"(r2), "=r"(r3) : "r"(addr));
}
__device__ __forceinline__ void mma_bf16(float* c, const uint32_t* a,
                                         uint32_t b0, uint32_t b1) {
    asm volatile(
        "mma.sync.aligned.m16n8k16.row.col.f32.bf16.bf16.f32 "
        "{%0,%1,%2,%3},{%4,%5,%6,%7},{%8,%9},{%0,%1,%2,%3};"
        : "+f"(c[0]), "+f"(c[1]), "+f"(c[2]), "+f"(c[3])
        : "r"(a[0]), "r"(a[1]), "r"(a[2]), "r"(a[3]), "r"(b0), "r"(b1));
}
__device__ __forceinline__ void cp16(uint32_t dst, const void* src) {
    asm volatile("cp.async.cg.shared.global [%0], [%1], 16;"
                 :: "r"(dst), "l"(src) : "memory");
}
// SW128 swizzle within a 16KB subtile of 128B rows
#define SW(b) ((b) ^ (((b) >> 3) & 0x70))

// ---------------------------------------------------------------------------
// Unified 3-pass bf16-split GEMM, 3-stage cp.async pipeline, 1 sync/chunk.
// CTA 128x128, 8 warps (32m x 64n), BK=32.
// Pass loop is OUTERMOST within each ng group so accumulator reuse distance
// is 4 HMMAs (hides HMMA RAW latency).
// ---------------------------------------------------------------------------
#define STG    32768
#define NSTAGE 3
#define SMEM_GEMM (512 + NSTAGE * STG)    // 98816

template <int MODE>
__global__ __launch_bounds__(256, 2) void gemm_kernel(const float* __restrict__ coef_in)
{
    constexpr int K = (MODE == 0) ? FDIM : EDIM;
    constexpr int NK = K / 32;

    extern __shared__ char smem[];
    const uint32_t smem_u = (uint32_t)__cvta_generic_to_shared(smem);
    float* scoef = (float*)smem;

    const int tid = threadIdx.x;
    const int wid = tid >> 5, lane = tid & 31;
    const int wm = wid & 3, wn = wid >> 2;
    const int m0 = blockIdx.x * 128, n0 = blockIdx.y * 128;

    const __nv_bfloat16 *Ah, *Al, *Bh, *Bl;
    if (MODE == 0) {
        Ah = g_fhi; Al = g_flo; Bh = g_whi; Bl = g_wlo;
    } else {
        Ah = g_hi; Al = g_lo;
        Bh = g_hi + (size_t)BQ * EDIM; Bl = g_lo + (size_t)BQ * EDIM;
    }

    if (tid < 128)
        scoef[tid] = (MODE == 0) ? coef_in[n0 + tid] : g_rh[n0 + tid];

    auto issue_load = [&](int chunk, int s) {
        const int k0 = chunk * 32;
        const uint32_t st = smem_u + 512 + s * STG;
#pragma unroll
        for (int t = 0; t < 8; t++) {
            int idx = t * 256 + tid;                // [0,2048)
            int mat = idx >> 10;                    // 0=A, 1=B
            int rid = (idx & 1023) >> 3;            // row 0..127
            int seg = idx & 7;                      // 0-3 hi, 4-7 lo
            int comp = seg >> 2, ks8 = seg & 3;
            size_t gofs = (size_t)((mat ? n0 : m0) + rid) * K + k0 + ks8 * 8;
            const __nv_bfloat16* src =
                mat ? (comp ? Bl : Bh) : (comp ? Al : Ah);
            uint32_t d = SW((uint32_t)(rid * 128 + seg * 16));
            cp16(st + mat * 16384 + d, src + gofs);
        }
        asm volatile("cp.async.commit_group;" ::: "memory");
    };

    float facc[2][8][4];
#pragma unroll
    for (int mt = 0; mt < 2; mt++)
#pragma unroll
        for (int nt = 0; nt < 8; nt++)
#pragma unroll
            for (int i = 0; i < 4; i++) facc[mt][nt][i] = 0.f;

    issue_load(0, 0);
    issue_load(1, 1);

    int s = 0;
    for (int chunk = 0; chunk < NK; chunk++) {
        if (chunk + 1 < NK) {
            asm volatile("cp.async.wait_group 1;" ::: "memory");
        } else {
            asm volatile("cp.async.wait_group 0;" ::: "memory");
        }
        __syncthreads();   // stage s ready; all warps done with stage (s+2)%3

        if (chunk + 2 < NK) issue_load(chunk + 2, (s + 2) % NSTAGE);

        const uint32_t st = smem_u + 512 + s * STG;
#pragma unroll
        for (int ks = 0; ks < 2; ks++) {
            const uint32_t kb = (uint32_t)(ks * 32 + (lane >> 4) * 16);
            uint32_t a[2][2][4];
#pragma unroll
            for (int comp = 0; comp < 2; comp++)
#pragma unroll
                for (int mt = 0; mt < 2; mt++) {
                    uint32_t row = wm * 32 + mt * 16 + (lane & 15);
                    ldsm4(a[comp][mt][0], a[comp][mt][1], a[comp][mt][2], a[comp][mt][3],
                          st + SW(row * 128 + comp * 64 + kb));
                }
#pragma unroll
            for (int ng = 0; ng < 4; ng++) {
                uint32_t nr = wn * 64 + ng * 16 + (lane & 15);
                uint32_t bh4[4], bl4[4];
                ldsm4(bh4[0], bh4[1], bh4[2], bh4[3],
                      st + 16384 + SW(nr * 128 + kb));
                ldsm4(bl4[0], bl4[1], bl4[2], bl4[3],
                      st + 16384 + SW(nr * 128 + 64 + kb));
                // pass-outer: accumulator reuse distance = 4 HMMAs
#pragma unroll
                for (int p = 0; p < 3; p++) {
                    const uint32_t (*aa)[4] = (p == 2) ? &a[1][0] : &a[0][0];
                    const uint32_t* bb = (p == 1) ? bl4 : bh4;
#pragma unroll
                    for (int mt = 0; mt < 2; mt++)
#pragma unroll
                        for (int h = 0; h < 2; h++)
                            mma_bf16(facc[mt][ng * 2 + h], aa[mt], bb[h], bb[2 + h]);
                }
            }
        }
        s = (s + 1) % NSTAGE;
    }

    if (MODE == 0) {
        // +bias, store fp32
#pragma unroll
        for (int mt = 0; mt < 2; mt++)
#pragma unroll
            for (int nt = 0; nt < 8; nt++)
#pragma unroll
                for (int p = 0; p < 2; p++) {
                    int row = m0 + wm * 32 + mt * 16 + p * 8 + (lane >> 2);
                    if (row >= REALROWS) continue;
                    int cl = wn * 64 + nt * 8 + (lane & 3) * 2;
                    float2 v;
                    v.x = facc[mt][nt][p * 2 + 0] + scoef[cl];
                    v.y = facc[mt][nt][p * 2 + 1] + scoef[cl + 1];
                    *(float2*)&g_XDe[(size_t)row * EDIM + n0 + cl] = v;
                }
    } else {
        // cube * rh, reduce over n
        float rsum[4] = {0.f, 0.f, 0.f, 0.f};
#pragma unroll
        for (int mt = 0; mt < 2; mt++)
#pragma unroll
            for (int nt = 0; nt < 8; nt++)
#pragma unroll
                for (int i = 0; i < 4; i++) {
                    int cl = wn * 64 + nt * 8 + (lane & 3) * 2 + (i & 1);
                    float a = facc[mt][nt][i];
                    rsum[mt * 2 + (i >> 1)] += a * a * a * scoef[cl];
                }
#pragma unroll
        for (int off = 1; off <= 2; off <<= 1)
#pragma unroll
            for (int k = 0; k < 4; k++)
                rsum[k] += __shfl_xor_sync(0xffffffffu, rsum[k], off);

        __syncthreads();                       // stages dead after this
        float* red = (float*)(smem + 512);
        if ((lane & 3) == 0) {
#pragma unroll
            for (int mt = 0; mt < 2; mt++)
#pragma unroll
                for (int h = 0; h < 2; h++)
                    red[wn * 128 + wm * 32 + mt * 16 + h * 8 + (lane >> 2)] =
                        rsum[mt * 2 + h];
        }
        __syncthreads();
        if (tid < 128)
            g_partial[(size_t)blockIdx.y * BQ + m0 + tid] = red[tid] + red[128 + tid];
    }
}

// ---------------------------------------------------------------------------
// Convert fp32 -> bf16 hi/lo. One launch: X, then D, then g_w regions.
// ---------------------------------------------------------------------------
#define NXD  (TOTROWS * FDIM)        // includes pad (never read, but safe)
#define NX   (BQ * FDIM)
#define NREAL (REALROWS * FDIM)
#define NW   (EDIM * FDIM)

__global__ void convert_all_kernel(const float* __restrict__ X,
                                   const float* __restrict__ D,
                                   const float* __restrict__ Wg)
{
    int i = blockIdx.x * blockDim.x + threadIdx.x;
    int stride = gridDim.x * blockDim.x;
    for (; i < NREAL + NW; i += stride) {
        float v;
        __nv_bfloat16 *dhi, *dlo;
        size_t o;
        if (i < NX)          { v = X[i];          dhi = g_fhi; dlo = g_flo; o = i; }
        else if (i < NREAL)  { v = D[i - NX];     dhi = g_fhi; dlo = g_flo; o = i; }
        else                 { v = Wg[i - NREAL]; dhi = g_whi; dlo = g_wlo; o = i - NREAL; }
        __nv_bfloat16 h = __float2bfloat16(v);
        dhi[o] = h;
        dlo[o] = __float2bfloat16(v - __bfloat162float(h));
    }
}

__global__ __launch_bounds__(128) void normalize_kernel()
{
    const int row = blockIdx.x;
    const float* p = g_XDe + (size_t)row * EDIM;
    const int t = threadIdx.x;
    float v[4];
    float ss = 0.f;
#pragma unroll
    for (int i = 0; i < 4; i++) { v[i] = p[t + i * 128]; ss += v[i] * v[i]; }
#pragma unroll
    for (int off = 16; off >= 1; off >>= 1)
        ss += __shfl_xor_sync(0xffffffffu, ss, off);
    __shared__ float red[4];
    if ((t & 31) == 0) red[t >> 5] = ss;
    __syncthreads();
    float inv = 1.f / fmaxf(sqrtf(red[0] + red[1] + red[2] + red[3]), 1e-12f);
#pragma unroll
    for (int i = 0; i < 4; i++) {
        float nv = v[i] * inv;
        __nv_bfloat16 h = __float2bfloat16(nv);
        g_hi[(size_t)row * EDIM + t + i * 128] = h;
        g_lo[(size_t)row * EDIM + t + i * 128] =
            __float2bfloat16(nv - __bfloat162float(h));
    }
}

__global__ void rh_kernel(const float* __restrict__ r,
                          const float* __restrict__ h_w,
                          const float* __restrict__ h_b)
{
    int n = blockIdx.x * blockDim.x + threadIdx.x;
    if (n < NEX) g_rh[n] = (2.f * r[n] - 1.f) * h_w[0] + h_b[0];
}

__global__ void reduce_kernel(float* __restrict__ out, int out_size)
{
    int b = blockIdx.x * blockDim.x + threadIdx.x;
    if (b >= BQ) return;
    float s = 0.f;
#pragma unroll 4
    for (int j = 0; j < NBN; j++) s += g_partial[(size_t)j * BQ + b];
    if (b < out_size) out[b] = s;
    if (BQ + b < out_size) out[BQ + b] = 1.f / (1.f + expf(-s));
}

// ---------------------------------------------------------------------------
extern "C" void kernel_launch(void* const* d_in, const int* in_sizes, int n_in,
                              void* d_out, int out_size)
{
    const float* X   = (const float*)d_in[0];
    const float* D   = (const float*)d_in[1];
    const float* r   = (const float*)d_in[2];
    const float* g_w = (const float*)d_in[3];
    const float* g_b = (const float*)d_in[4];
    const float* h_w = (const float*)d_in[5];
    const float* h_b = (const float*)d_in[6];
    float* out = (float*)d_out;

    cudaFuncSetAttribute(gemm_kernel<0>,
                         cudaFuncAttributeMaxDynamicSharedMemorySize, SMEM_GEMM);
    cudaFuncSetAttribute(gemm_kernel<1>,
                         cudaFuncAttributeMaxDynamicSharedMemorySize, SMEM_GEMM);

    convert_all_kernel<<<1184, 256>>>(X, D, g_w);

    rh_kernel<<<(NEX + 255) / 256, 256>>>(r, h_w, h_b);

    dim3 ge(TOTROWS / 128, EDIM / 128);        // (189, 4)
    gemm_kernel<0><<<ge, 256, SMEM_GEMM>>>(g_b);

    normalize_kernel<<<REALROWS, 128>>>();

    dim3 gm(BQ / 128, NPAD / 128);             // (32, 157)
    gemm_kernel<1><<<gm, 256, SMEM_GEMM>>>(nullptr);

    reduce_kernel<<<(BQ + 127) / 128, 128>>>(out, out_size);
}

// round 10
// speedup vs baseline: 2.9999x; 1.0014x over previous
#include <cuda_runtime.h>
#include <cuda_bf16.h>
#include <stdint.h>
#include <math.h>

// ---------------- problem dims ----------------
#define BQ       4096
#define NEX      20000
#define NPAD     20096               // 157 * 128
#define FDIM     768
#define EDIM     512
#define TOTROWS  (BQ + NPAD)         // 24192
#define REALROWS (BQ + NEX)          // 24096
#define NBN      157

// ---------------- scratch (.bss, zero-init; pads stay 0) ----------------
__device__ float         g_XDe[(size_t)TOTROWS * EDIM];   // fp32 embeds (pre-norm)
__device__ __nv_bfloat16 g_fhi[(size_t)TOTROWS * FDIM];   // [X;D] features hi
__device__ __nv_bfloat16 g_flo[(size_t)TOTROWS * FDIM];   // lo
__device__ __nv_bfloat16 g_whi[(size_t)EDIM * FDIM];      // g_w hi
__device__ __nv_bfloat16 g_wlo[(size_t)EDIM * FDIM];
__device__ __nv_bfloat16 g_hi[(size_t)TOTROWS * EDIM];    // normalized embeds hi
__device__ __nv_bfloat16 g_lo[(size_t)TOTROWS * EDIM];    // lo
__device__ float         g_rh[NPAD];                       // rh (pad = 0)
__device__ float         g_partial[NBN * BQ];

// ---------------- helpers (base-target instructions only) ----------------
__device__ __forceinline__ void ldsm4(uint32_t& r0, uint32_t& r1,
                                      uint32_t& r2, uint32_t& r3, uint32_t addr) {
    asm volatile("ldmatrix.sync.aligned.m8n8.x4.shared.b16 {%0,%1,%2,%3}, [%4];"
                 : "=r"(r0), "=r"(r1), "=r"(r2), "=r"(r3) : "r"(addr));
}
__device__ __forceinline__ void mma_bf16(float* c, const uint32_t* a,
                                         uint32_t b0, uint32_t b1) {
    asm volatile(
        "mma.sync.aligned.m16n8k16.row.col.f32.bf16.bf16.f32 "
        "{%0,%1,%2,%3},{%4,%5,%6,%7},{%8,%9},{%0,%1,%2,%3};"
        : "+f"(c[0]), "+f"(c[1]), "+f"(c[2]), "+f"(c[3])
        : "r"(a[0]), "r"(a[1]), "r"(a[2]), "r"(a[3]), "r"(b0), "r"(b1));
}
__device__ __forceinline__ void cp16(uint32_t dst, const void* src) {
    asm volatile("cp.async.cg.shared.global [%0], [%1], 16;"
                 :: "r"(dst), "l"(src) : "memory");
}
// SW128 swizzle within a 16KB subtile of 128B rows
#define SW(b) ((b) ^ (((b) >> 3) & 0x70))

// ---------------------------------------------------------------------------
// Unified 3-pass bf16-split GEMM, 3-stage cp.async pipeline, 1 sync/chunk.
// CTA 128x128, 8 warps (32m x 64n), BK=32.  (R6-proven core.)
// MODE 0 (embed): A=[X;D] bf16 hi/lo (K=768), B=g_w; epi: +bias -> g_XDe.
// MODE 1 (main) : A=query embeds, B=exemplar embeds (K=512);
//                 epi: cube * rh, reduce over n -> g_partial.
// ---------------------------------------------------------------------------
#define STG    32768
#define NSTAGE 3
#define SMEM_GEMM (512 + NSTAGE * STG)    // 98816

template <int MODE>
__global__ __launch_bounds__(256, 2) void gemm_kernel(const float* __restrict__ coef_in)
{
    constexpr int K = (MODE == 0) ? FDIM : EDIM;
    constexpr int NK = K / 32;

    extern __shared__ char smem[];
    const uint32_t smem_u = (uint32_t)__cvta_generic_to_shared(smem);
    float* scoef = (float*)smem;

    const int tid = threadIdx.x;
    const int wid = tid >> 5, lane = tid & 31;
    const int wm = wid & 3, wn = wid >> 2;
    const int m0 = blockIdx.x * 128, n0 = blockIdx.y * 128;

    const __nv_bfloat16 *Ah, *Al, *Bh, *Bl;
    if (MODE == 0) {
        Ah = g_fhi; Al = g_flo; Bh = g_whi; Bl = g_wlo;
    } else {
        Ah = g_hi; Al = g_lo;
        Bh = g_hi + (size_t)BQ * EDIM; Bl = g_lo + (size_t)BQ * EDIM;
    }

    if (tid < 128)
        scoef[tid] = (MODE == 0) ? coef_in[n0 + tid] : g_rh[n0 + tid];

    auto issue_load = [&](int chunk, int s) {
        const int k0 = chunk * 32;
        const uint32_t st = smem_u + 512 + s * STG;
#pragma unroll
        for (int t = 0; t < 8; t++) {
            int idx = t * 256 + tid;                // [0,2048)
            int mat = idx >> 10;                    // 0=A, 1=B
            int rid = (idx & 1023) >> 3;            // row 0..127
            int seg = idx & 7;                      // 0-3 hi, 4-7 lo
            int comp = seg >> 2, ks8 = seg & 3;
            size_t gofs = (size_t)((mat ? n0 : m0) + rid) * K + k0 + ks8 * 8;
            const __nv_bfloat16* src =
                mat ? (comp ? Bl : Bh) : (comp ? Al : Ah);
            uint32_t d = SW((uint32_t)(rid * 128 + seg * 16));
            cp16(st + mat * 16384 + d, src + gofs);
        }
        asm volatile("cp.async.commit_group;" ::: "memory");
    };

    float facc[2][8][4];
#pragma unroll
    for (int mt = 0; mt < 2; mt++)
#pragma unroll
        for (int nt = 0; nt < 8; nt++)
#pragma unroll
            for (int i = 0; i < 4; i++) facc[mt][nt][i] = 0.f;

    issue_load(0, 0);
    issue_load(1, 1);

    int s = 0;
    for (int chunk = 0; chunk < NK; chunk++) {
        if (chunk + 1 < NK) {
            asm volatile("cp.async.wait_group 1;" ::: "memory");
        } else {
            asm volatile("cp.async.wait_group 0;" ::: "memory");
        }
        __syncthreads();   // stage s ready; all warps done with stage (s+2)%3

        if (chunk + 2 < NK) issue_load(chunk + 2, (s + 2) % NSTAGE);

        const uint32_t st = smem_u + 512 + s * STG;
#pragma unroll
        for (int ks = 0; ks < 2; ks++) {
            const uint32_t kb = (uint32_t)(ks * 32 + (lane >> 4) * 16);
            uint32_t a[2][2][4];
#pragma unroll
            for (int comp = 0; comp < 2; comp++)
#pragma unroll
                for (int mt = 0; mt < 2; mt++) {
                    uint32_t row = wm * 32 + mt * 16 + (lane & 15);
                    ldsm4(a[comp][mt][0], a[comp][mt][1], a[comp][mt][2], a[comp][mt][3],
                          st + SW(row * 128 + comp * 64 + kb));
                }
#pragma unroll
            for (int ng = 0; ng < 4; ng++) {
                uint32_t nr = wn * 64 + ng * 16 + (lane & 15);
                uint32_t bh4[4], bl4[4];
                ldsm4(bh4[0], bh4[1], bh4[2], bh4[3],
                      st + 16384 + SW(nr * 128 + kb));
                ldsm4(bl4[0], bl4[1], bl4[2], bl4[3],
                      st + 16384 + SW(nr * 128 + 64 + kb));
#pragma unroll
                for (int p = 0; p < 3; p++) {
                    const uint32_t (*aa)[4] = (p == 2) ? &a[1][0] : &a[0][0];
                    const uint32_t* bb = (p == 1) ? bl4 : bh4;
#pragma unroll
                    for (int mt = 0; mt < 2; mt++)
#pragma unroll
                        for (int h = 0; h < 2; h++)
                            mma_bf16(facc[mt][ng * 2 + h], aa[mt], bb[h], bb[2 + h]);
                }
            }
        }
        s = (s + 1) % NSTAGE;
    }

    if (MODE == 0) {
        // +bias, store fp32
#pragma unroll
        for (int mt = 0; mt < 2; mt++)
#pragma unroll
            for (int nt = 0; nt < 8; nt++)
#pragma unroll
                for (int p = 0; p < 2; p++) {
                    int row = m0 + wm * 32 + mt * 16 + p * 8 + (lane >> 2);
                    if (row >= REALROWS) continue;
                    int cl = wn * 64 + nt * 8 + (lane & 3) * 2;
                    float2 v;
                    v.x = facc[mt][nt][p * 2 + 0] + scoef[cl];
                    v.y = facc[mt][nt][p * 2 + 1] + scoef[cl + 1];
                    *(float2*)&g_XDe[(size_t)row * EDIM + n0 + cl] = v;
                }
    } else {
        // cube * rh, reduce over n
        float rsum[4] = {0.f, 0.f, 0.f, 0.f};
#pragma unroll
        for (int mt = 0; mt < 2; mt++)
#pragma unroll
            for (int nt = 0; nt < 8; nt++)
#pragma unroll
                for (int i = 0; i < 4; i++) {
                    int cl = wn * 64 + nt * 8 + (lane & 3) * 2 + (i & 1);
                    float a = facc[mt][nt][i];
                    rsum[mt * 2 + (i >> 1)] += a * a * a * scoef[cl];
                }
#pragma unroll
        for (int off = 1; off <= 2; off <<= 1)
#pragma unroll
            for (int k = 0; k < 4; k++)
                rsum[k] += __shfl_xor_sync(0xffffffffu, rsum[k], off);

        __syncthreads();                       // stages dead after this
        float* red = (float*)(smem + 512);
        if ((lane & 3) == 0) {
#pragma unroll
            for (int mt = 0; mt < 2; mt++)
#pragma unroll
                for (int h = 0; h < 2; h++)
                    red[wn * 128 + wm * 32 + mt * 16 + h * 8 + (lane >> 2)] =
                        rsum[mt * 2 + h];
        }
        __syncthreads();
        if (tid < 128)
            g_partial[(size_t)blockIdx.y * BQ + m0 + tid] = red[tid] + red[128 + tid];
    }
}

// ---------------------------------------------------------------------------
// Convert fp32 -> bf16 hi/lo for X, D, g_w; rh fused at the tail.
// (Fusing rh keeps the launch count such that the main GEMM is launch #3,
//  which is the slot ncu captures.)
// ---------------------------------------------------------------------------
#define NX    (BQ * FDIM)
#define NREAL (REALROWS * FDIM)
#define NW    (EDIM * FDIM)
#define NTOT  (NREAL + NW + NEX)

__global__ void convert_all_kernel(const float* __restrict__ X,
                                   const float* __restrict__ D,
                                   const float* __restrict__ Wg,
                                   const float* __restrict__ r,
                                   const float* __restrict__ h_w,
                                   const float* __restrict__ h_b)
{
    int i = blockIdx.x * blockDim.x + threadIdx.x;
    int stride = gridDim.x * blockDim.x;
    for (; i < NTOT; i += stride) {
        if (i < NREAL + NW) {
            float v;
            __nv_bfloat16 *dhi, *dlo;
            size_t o;
            if (i < NX)          { v = X[i];          dhi = g_fhi; dlo = g_flo; o = i; }
            else if (i < NREAL)  { v = D[i - NX];     dhi = g_fhi; dlo = g_flo; o = i; }
            else                 { v = Wg[i - NREAL]; dhi = g_whi; dlo = g_wlo; o = i - NREAL; }
            __nv_bfloat16 h = __float2bfloat16(v);
            dhi[o] = h;
            dlo[o] = __float2bfloat16(v - __bfloat162float(h));
        } else {
            int n = i - (NREAL + NW);
            g_rh[n] = (2.f * r[n] - 1.f) * h_w[0] + h_b[0];
        }
    }
}

__global__ __launch_bounds__(128) void normalize_kernel()
{
    const int row = blockIdx.x;
    const float* p = g_XDe + (size_t)row * EDIM;
    const int t = threadIdx.x;
    float v[4];
    float ss = 0.f;
#pragma unroll
    for (int i = 0; i < 4; i++) { v[i] = p[t + i * 128]; ss += v[i] * v[i]; }
#pragma unroll
    for (int off = 16; off >= 1; off >>= 1)
        ss += __shfl_xor_sync(0xffffffffu, ss, off);
    __shared__ float red[4];
    if ((t & 31) == 0) red[t >> 5] = ss;
    __syncthreads();
    float inv = 1.f / fmaxf(sqrtf(red[0] + red[1] + red[2] + red[3]), 1e-12f);
#pragma unroll
    for (int i = 0; i < 4; i++) {
        float nv = v[i] * inv;
        __nv_bfloat16 h = __float2bfloat16(nv);
        g_hi[(size_t)row * EDIM + t + i * 128] = h;
        g_lo[(size_t)row * EDIM + t + i * 128] =
            __float2bfloat16(nv - __bfloat162float(h));
    }
}

__global__ void reduce_kernel(float* __restrict__ out, int out_size)
{
    int b = blockIdx.x * blockDim.x + threadIdx.x;
    if (b >= BQ) return;
    float s = 0.f;
#pragma unroll 4
    for (int j = 0; j < NBN; j++) s += g_partial[(size_t)j * BQ + b];
    if (b < out_size) out[b] = s;
    if (BQ + b < out_size) out[BQ + b] = 1.f / (1.f + expf(-s));
}

// ---------------------------------------------------------------------------
extern "C" void kernel_launch(void* const* d_in, const int* in_sizes, int n_in,
                              void* d_out, int out_size)
{
    const float* X   = (const float*)d_in[0];
    const float* D   = (const float*)d_in[1];
    const float* r   = (const float*)d_in[2];
    const float* g_w = (const float*)d_in[3];
    const float* g_b = (const float*)d_in[4];
    const float* h_w = (const float*)d_in[5];
    const float* h_b = (const float*)d_in[6];
    float* out = (float*)d_out;

    cudaFuncSetAttribute(gemm_kernel<0>,
                         cudaFuncAttributeMaxDynamicSharedMemorySize, SMEM_GEMM);
    cudaFuncSetAttribute(gemm_kernel<1>,
                         cudaFuncAttributeMaxDynamicSharedMemorySize, SMEM_GEMM);

    // launch 0: convert + rh
    convert_all_kernel<<<1184, 256>>>(X, D, g_w, r, h_w, h_b);

    // launch 1: embed GEMM (bf16 3-pass)
    dim3 ge(TOTROWS / 128, EDIM / 128);        // (189, 4)
    gemm_kernel<0><<<ge, 256, SMEM_GEMM>>>(g_b);

    // launch 2: normalize -> bf16 hi/lo
    normalize_kernel<<<REALROWS, 128>>>();

    // launch 3: main GEMM (fused cube*rh + n-reduction)  <- ncu capture slot
    dim3 gm(BQ / 128, NPAD / 128);             // (32, 157)
    gemm_kernel<1><<<gm, 256, SMEM_GEMM>>>(nullptr);

    // launch 4: final reduce + sigmoid
    reduce_kernel<<<(BQ + 127) / 128, 128>>>(out, out_size);
}

// round 11
// speedup vs baseline: 3.0658x; 1.0220x over previous
#include <cuda_runtime.h>
#include <cuda_bf16.h>
#include <stdint.h>
#include <math.h>

// ---------------- problem dims ----------------
#define BQ       4096
#define NEX      20000
#define NPAD     20096               // 157 * 128
#define FDIM     768
#define EDIM     512
#define TOTROWS  (BQ + NPAD)         // 24192
#define REALROWS (BQ + NEX)          // 24096
#define NBN      157

// ---------------- scratch (.bss, zero-init; pads stay 0) ----------------
__device__ float         g_XDe[(size_t)TOTROWS * EDIM];   // fp32 embeds (pre-norm)
__device__ __nv_bfloat16 g_fhi[(size_t)TOTROWS * FDIM];   // [X;D] features hi
__device__ __nv_bfloat16 g_flo[(size_t)TOTROWS * FDIM];   // lo
__device__ __nv_bfloat16 g_whi[(size_t)EDIM * FDIM];      // g_w hi
__device__ __nv_bfloat16 g_wlo[(size_t)EDIM * FDIM];
__device__ __nv_bfloat16 g_hi[(size_t)TOTROWS * EDIM];    // normalized embeds hi
__device__ __nv_bfloat16 g_lo[(size_t)TOTROWS * EDIM];    // lo
__device__ float         g_rh[NPAD];                       // rh (pad = 0)
__device__ float         g_partial[NBN * BQ];

// ---------------- helpers (base-target instructions only) ----------------
__device__ __forceinline__ void ldsm4(uint32_t& r0, uint32_t& r1,
                                      uint32_t& r2, uint32_t& r3, uint32_t addr) {
    asm volatile("ldmatrix.sync.aligned.m8n8.x4.shared.b16 {%0,%1,%2,%3}, [%4];"
                 : "=r"(r0), "=r"(r1), "=r"(r2), "=r"(r3) : "r"(addr));
}
__device__ __forceinline__ void mma_bf16(float* c, const uint32_t* a,
                                         uint32_t b0, uint32_t b1) {
    asm volatile(
        "mma.sync.aligned.m16n8k16.row.col.f32.bf16.bf16.f32 "
        "{%0,%1,%2,%3},{%4,%5,%6,%7},{%8,%9},{%0,%1,%2,%3};"
        : "+f"(c[0]), "+f"(c[1]), "+f"(c[2]), "+f"(c[3])
        : "r"(a[0]), "r"(a[1]), "r"(a[2]), "r"(a[3]), "r"(b0), "r"(b1));
}
__device__ __forceinline__ void cp16(uint32_t dst, const void* src) {
    asm volatile("cp.async.cg.shared.global [%0], [%1], 16;"
                 :: "r"(dst), "l"(src) : "memory");
}
// SW128 swizzle within a 16KB subtile of 128B rows
#define SW(b) ((b) ^ (((b) >> 3) & 0x70))

// ---------------------------------------------------------------------------
// Unified 3-pass bf16-split GEMM, 3-stage cp.async pipeline, 1 sync/chunk,
// B-fragment double-buffer across ng, cp.async issued off the critical path.
// CTA 128x128, 8 warps (32m x 64n), BK=32.
// ---------------------------------------------------------------------------
#define STG    32768
#define NSTAGE 3
#define SMEM_GEMM (512 + NSTAGE * STG)    // 98816

template <int MODE>
__global__ __launch_bounds__(256, 2) void gemm_kernel(const float* __restrict__ coef_in)
{
    constexpr int K = (MODE == 0) ? FDIM : EDIM;
    constexpr int NK = K / 32;

    extern __shared__ char smem[];
    const uint32_t smem_u = (uint32_t)__cvta_generic_to_shared(smem);
    float* scoef = (float*)smem;

    const int tid = threadIdx.x;
    const int wid = tid >> 5, lane = tid & 31;
    const int wm = wid & 3, wn = wid >> 2;
    const int m0 = blockIdx.x * 128, n0 = blockIdx.y * 128;

    const __nv_bfloat16 *Ah, *Al, *Bh, *Bl;
    if (MODE == 0) {
        Ah = g_fhi; Al = g_flo; Bh = g_whi; Bl = g_wlo;
    } else {
        Ah = g_hi; Al = g_lo;
        Bh = g_hi + (size_t)BQ * EDIM; Bl = g_lo + (size_t)BQ * EDIM;
    }

    if (tid < 128)
        scoef[tid] = (MODE == 0) ? coef_in[n0 + tid] : g_rh[n0 + tid];

    auto issue_load = [&](int chunk, int st_idx) {
        const int k0 = chunk * 32;
        const uint32_t st = smem_u + 512 + st_idx * STG;
#pragma unroll
        for (int t = 0; t < 8; t++) {
            int idx = t * 256 + tid;                // [0,2048)
            int mat = idx >> 10;                    // 0=A, 1=B
            int rid = (idx & 1023) >> 3;            // row 0..127
            int seg = idx & 7;                      // 0-3 hi, 4-7 lo
            int comp = seg >> 2, ks8 = seg & 3;
            size_t gofs = (size_t)((mat ? n0 : m0) + rid) * K + k0 + ks8 * 8;
            const __nv_bfloat16* src =
                mat ? (comp ? Bl : Bh) : (comp ? Al : Ah);
            uint32_t d = SW((uint32_t)(rid * 128 + seg * 16));
            cp16(st + mat * 16384 + d, src + gofs);
        }
        asm volatile("cp.async.commit_group;" ::: "memory");
    };

    float facc[2][8][4];
#pragma unroll
    for (int mt = 0; mt < 2; mt++)
#pragma unroll
        for (int nt = 0; nt < 8; nt++)
#pragma unroll
            for (int i = 0; i < 4; i++) facc[mt][nt][i] = 0.f;

    // one ks slice: a-frags, b double-buffered across ng; optionally issue
    // the chunk+2 cp.async AFTER the first ldsm batch (off the critical path).
    auto compute_ks = [&](uint32_t st, int ks, int issue_chunk, int issue_stage) {
        const uint32_t kb = (uint32_t)(ks * 32 + (lane >> 4) * 16);
        uint32_t a[2][2][4];
#pragma unroll
        for (int comp = 0; comp < 2; comp++)
#pragma unroll
            for (int mt = 0; mt < 2; mt++) {
                uint32_t row = wm * 32 + mt * 16 + (lane & 15);
                ldsm4(a[comp][mt][0], a[comp][mt][1], a[comp][mt][2], a[comp][mt][3],
                      st + SW(row * 128 + comp * 64 + kb));
            }
        uint32_t bh[2][4], bl[2][4];
        {
            uint32_t nr = wn * 64 + (lane & 15);
            ldsm4(bh[0][0], bh[0][1], bh[0][2], bh[0][3],
                  st + 16384 + SW(nr * 128 + kb));
            ldsm4(bl[0][0], bl[0][1], bl[0][2], bl[0][3],
                  st + 16384 + SW(nr * 128 + 64 + kb));
        }
        if (issue_chunk >= 0) issue_load(issue_chunk, issue_stage);
#pragma unroll
        for (int ng = 0; ng < 4; ng++) {
            const int cur = ng & 1, nxt = cur ^ 1;
            if (ng < 3) {
                uint32_t nr = wn * 64 + (ng + 1) * 16 + (lane & 15);
                ldsm4(bh[nxt][0], bh[nxt][1], bh[nxt][2], bh[nxt][3],
                      st + 16384 + SW(nr * 128 + kb));
                ldsm4(bl[nxt][0], bl[nxt][1], bl[nxt][2], bl[nxt][3],
                      st + 16384 + SW(nr * 128 + 64 + kb));
            }
#pragma unroll
            for (int p = 0; p < 3; p++) {
                const uint32_t (*aa)[4] = (p == 2) ? &a[1][0] : &a[0][0];
                const uint32_t* bb = (p == 1) ? bl[cur] : bh[cur];
#pragma unroll
                for (int mt = 0; mt < 2; mt++)
#pragma unroll
                    for (int h = 0; h < 2; h++)
                        mma_bf16(facc[mt][ng * 2 + h], aa[mt], bb[h], bb[2 + h]);
            }
        }
    };

    issue_load(0, 0);
    issue_load(1, 1);

    int s = 0;
    for (int chunk = 0; chunk < NK; chunk++) {
        if (chunk + 1 < NK) {
            asm volatile("cp.async.wait_group 1;" ::: "memory");
        } else {
            asm volatile("cp.async.wait_group 0;" ::: "memory");
        }
        __syncthreads();   // stage s ready; all warps done with stage (s+2)%3

        const uint32_t st = smem_u + 512 + s * STG;
        const int ic = (chunk + 2 < NK) ? (chunk + 2) : -1;
        compute_ks(st, 0, ic, (s + 2) % NSTAGE);
        compute_ks(st, 1, -1, 0);
        s = (s + 1) % NSTAGE;
    }

    if (MODE == 0) {
        // +bias, store fp32
#pragma unroll
        for (int mt = 0; mt < 2; mt++)
#pragma unroll
            for (int nt = 0; nt < 8; nt++)
#pragma unroll
                for (int p = 0; p < 2; p++) {
                    int row = m0 + wm * 32 + mt * 16 + p * 8 + (lane >> 2);
                    if (row >= REALROWS) continue;
                    int cl = wn * 64 + nt * 8 + (lane & 3) * 2;
                    float2 v;
                    v.x = facc[mt][nt][p * 2 + 0] + scoef[cl];
                    v.y = facc[mt][nt][p * 2 + 1] + scoef[cl + 1];
                    *(float2*)&g_XDe[(size_t)row * EDIM + n0 + cl] = v;
                }
    } else {
        // cube * rh, reduce over n
        float rsum[4] = {0.f, 0.f, 0.f, 0.f};
#pragma unroll
        for (int mt = 0; mt < 2; mt++)
#pragma unroll
            for (int nt = 0; nt < 8; nt++)
#pragma unroll
                for (int i = 0; i < 4; i++) {
                    int cl = wn * 64 + nt * 8 + (lane & 3) * 2 + (i & 1);
                    float a = facc[mt][nt][i];
                    rsum[mt * 2 + (i >> 1)] += a * a * a * scoef[cl];
                }
#pragma unroll
        for (int off = 1; off <= 2; off <<= 1)
#pragma unroll
            for (int k = 0; k < 4; k++)
                rsum[k] += __shfl_xor_sync(0xffffffffu, rsum[k], off);

        __syncthreads();                       // stages dead after this
        float* red = (float*)(smem + 512);
        if ((lane & 3) == 0) {
#pragma unroll
            for (int mt = 0; mt < 2; mt++)
#pragma unroll
                for (int h = 0; h < 2; h++)
                    red[wn * 128 + wm * 32 + mt * 16 + h * 8 + (lane >> 2)] =
                        rsum[mt * 2 + h];
        }
        __syncthreads();
        if (tid < 128)
            g_partial[(size_t)blockIdx.y * BQ + m0 + tid] = red[tid] + red[128 + tid];
    }
}

// ---------------------------------------------------------------------------
// Convert fp32 -> bf16 hi/lo (float4 vectorized); rh fused at the tail.
// All three regions are multiples of 4 elements, so each float4 stays inside
// one region.
// ---------------------------------------------------------------------------
#define NX    (BQ * FDIM)
#define NREAL (REALROWS * FDIM)
#define NW    (EDIM * FDIM)
#define NV4   ((NREAL + NW) / 4)

__global__ void convert_all_kernel(const float* __restrict__ X,
                                   const float* __restrict__ D,
                                   const float* __restrict__ Wg,
                                   const float* __restrict__ r,
                                   const float* __restrict__ h_w,
                                   const float* __restrict__ h_b)
{
    const int tid0 = blockIdx.x * blockDim.x + threadIdx.x;
    const int stride = gridDim.x * blockDim.x;

    for (int j = tid0; j < NV4; j += stride) {
        const int e = j * 4;
        float4 v;
        __nv_bfloat16 *dhi, *dlo;
        int o;
        if (e < NX)          { v = *(const float4*)(X + e);            dhi = g_fhi; dlo = g_flo; o = e; }
        else if (e < NREAL)  { v = *(const float4*)(D + (e - NX));     dhi = g_fhi; dlo = g_flo; o = e; }
        else                 { v = *(const float4*)(Wg + (e - NREAL)); dhi = g_whi; dlo = g_wlo; o = e - NREAL; }
        __nv_bfloat16 h0 = __float2bfloat16(v.x), h1 = __float2bfloat16(v.y);
        __nv_bfloat16 h2 = __float2bfloat16(v.z), h3 = __float2bfloat16(v.w);
        __nv_bfloat162 H0; H0.x = h0; H0.y = h1;
        __nv_bfloat162 H1; H1.x = h2; H1.y = h3;
        __nv_bfloat162 L0, L1;
        L0.x = __float2bfloat16(v.x - __bfloat162float(h0));
        L0.y = __float2bfloat16(v.y - __bfloat162float(h1));
        L1.x = __float2bfloat16(v.z - __bfloat162float(h2));
        L1.y = __float2bfloat16(v.w - __bfloat162float(h3));
        *(__nv_bfloat162*)&dhi[o]     = H0;
        *(__nv_bfloat162*)&dhi[o + 2] = H1;
        *(__nv_bfloat162*)&dlo[o]     = L0;
        *(__nv_bfloat162*)&dlo[o + 2] = L1;
    }
    for (int n = tid0; n < NEX; n += stride)
        g_rh[n] = (2.f * r[n] - 1.f) * h_w[0] + h_b[0];
}

__global__ __launch_bounds__(128) void normalize_kernel()
{
    const int row = blockIdx.x;
    const float* p = g_XDe + (size_t)row * EDIM;
    const int t = threadIdx.x;
    float v[4];
    float ss = 0.f;
#pragma unroll
    for (int i = 0; i < 4; i++) { v[i] = p[t + i * 128]; ss += v[i] * v[i]; }
#pragma unroll
    for (int off = 16; off >= 1; off >>= 1)
        ss += __shfl_xor_sync(0xffffffffu, ss, off);
    __shared__ float red[4];
    if ((t & 31) == 0) red[t >> 5] = ss;
    __syncthreads();
    float inv = 1.f / fmaxf(sqrtf(red[0] + red[1] + red[2] + red[3]), 1e-12f);
#pragma unroll
    for (int i = 0; i < 4; i++) {
        float nv = v[i] * inv;
        __nv_bfloat16 h = __float2bfloat16(nv);
        g_hi[(size_t)row * EDIM + t + i * 128] = h;
        g_lo[(size_t)row * EDIM + t + i * 128] =
            __float2bfloat16(nv - __bfloat162float(h));
    }
}

__global__ void reduce_kernel(float* __restrict__ out, int out_size)
{
    int b = blockIdx.x * blockDim.x + threadIdx.x;
    if (b >= BQ) return;
    float s = 0.f;
#pragma unroll 4
    for (int j = 0; j < NBN; j++) s += g_partial[(size_t)j * BQ + b];
    if (b < out_size) out[b] = s;
    if (BQ + b < out_size) out[BQ + b] = 1.f / (1.f + expf(-s));
}

// ---------------------------------------------------------------------------
extern "C" void kernel_launch(void* const* d_in, const int* in_sizes, int n_in,
                              void* d_out, int out_size)
{
    const float* X   = (const float*)d_in[0];
    const float* D   = (const float*)d_in[1];
    const float* r   = (const float*)d_in[2];
    const float* g_w = (const float*)d_in[3];
    const float* g_b = (const float*)d_in[4];
    const float* h_w = (const float*)d_in[5];
    const float* h_b = (const float*)d_in[6];
    float* out = (float*)d_out;

    cudaFuncSetAttribute(gemm_kernel<0>,
                         cudaFuncAttributeMaxDynamicSharedMemorySize, SMEM_GEMM);
    cudaFuncSetAttribute(gemm_kernel<1>,
                         cudaFuncAttributeMaxDynamicSharedMemorySize, SMEM_GEMM);

    // launch 0: convert + rh
    convert_all_kernel<<<1184, 256>>>(X, D, g_w, r, h_w, h_b);

    // launch 1: embed GEMM (bf16 3-pass)
    dim3 ge(TOTROWS / 128, EDIM / 128);        // (189, 4)
    gemm_kernel<0><<<ge, 256, SMEM_GEMM>>>(g_b);

    // launch 2: normalize -> bf16 hi/lo
    normalize_kernel<<<REALROWS, 128>>>();

    // launch 3: main GEMM (fused cube*rh + n-reduction)  <- ncu capture slot
    dim3 gm(BQ / 128, NPAD / 128);             // (32, 157)
    gemm_kernel<1><<<gm, 256, SMEM_GEMM>>>(nullptr);

    // launch 4: final reduce + sigmoid
    reduce_kernel<<<(BQ + 127) / 128, 128>>>(out, out_size);
}